// round 13
// baseline (speedup 1.0000x reference)
#include <cuda_runtime.h>
#include <cuda_bf16.h>
#include <cstdint>

#define N_AST   200000
#define N_TEST  10000
#define HD      128
#define NLAYERS 5

// ---------------- scratch (device globals; no allocation allowed) ----------
#define F_HA   0u
#define F_HB   25600000u
#define F_SH   51200000u      // Sh bf16
#define F_SL   64000000u      // Sl bf16
#define F_MTA  76800000u
#define F_XTA  102400000u
#define F_STB  103680000u
#define F_HTA  104960000u
#define F_HTB  106240000u
#define F_WS   107520000u     // Wh/Wl pre-split (81920 floats)
#define F_WC   107601920u     // Wch/Wcl pre-split (16384 floats)
#define F_TOT  107618304u
__device__ float g_f[F_TOT];

#define I_OFF_AA 0
#define I_OFF_TA 200001
#define I_OFF_AT 400002
#define I_CUR_AA 410003
#define I_CUR_TA 610003
#define I_CUR_AT 810003
#define I_CSR_AA 820013
#define I_CSR_TA 2820013
#define I_CSR_AT 3320013
#define I_PART0  3820013
#define I_POFF0  3820813
#define I_PART1  3821614
#define I_POFF1  3822414
#define I_PART2  3823215
#define I_POFF2  3824015
#define I_TOT    3824816
__device__ int g_i[I_TOT];

static inline int div_up(int a, int b) { return (a + b - 1) / b; }

#define F_ADDIN  1
#define F_BIAS   2
#define F_RELU   4
#define F_ADDRES 8

// ---------------- streams/events (static init; not device-memory allocs) ----
#define NEV 40
struct SxInit {
    cudaStream_t s1, s2;
    cudaEvent_t ev[NEV];
    SxInit() {
        s1 = nullptr; s2 = nullptr;
        cudaStreamCreateWithFlags(&s1, cudaStreamNonBlocking);
        cudaStreamCreateWithFlags(&s2, cudaStreamNonBlocking);
        for (int i = 0; i < NEV; i++) {
            ev[i] = nullptr;
            cudaEventCreateWithFlags(&ev[i], cudaEventDisableTiming);
        }
    }
};
static SxInit g_sx;
#define EV_ROOT  0
#define EV_ENC   1
#define EV_INITT 2
#define EV_MMA(l)   (3 + (l))              // 3..7 (l=0..3 used; 4 unused)
#define EV_FIN   8
#define EV_AT(l)    (9 + (l))              // 9..12
#define EV_AGG(l,c) (13 + (l) * 4 + (c))   // 13..32

// ---------------- small utility kernels ------------------------------------
__global__ void k_zero_int(int* __restrict__ p, int n) {
    int i = blockIdx.x * blockDim.x + threadIdx.x;
    if (i < n) p[i] = 0;
}
__global__ void k_hist(const int* __restrict__ dst, int* __restrict__ deg, int E) {
    int e = blockIdx.x * blockDim.x + threadIdx.x;
    if (e < E) atomicAdd(&deg[dst[e]], 1);
}

__global__ void k_blocksum(const int* __restrict__ v, int* __restrict__ part, int n) {
    __shared__ int ws[32];
    int t = threadIdx.x;
    int i = blockIdx.x * 1024 + t;
    int x = (i < n) ? v[i] : 0;
    #pragma unroll
    for (int o = 16; o; o >>= 1) x += __shfl_xor_sync(0xffffffffu, x, o);
    if ((t & 31) == 0) ws[t >> 5] = x;
    __syncthreads();
    if (t < 32) {
        int y = ws[t];
        #pragma unroll
        for (int o = 16; o; o >>= 1) y += __shfl_xor_sync(0xffffffffu, y, o);
        if (t == 0) part[blockIdx.x] = y;
    }
}
__global__ void k_exscan(const int* __restrict__ v, int* __restrict__ offs, int n) {
    __shared__ int wsum[32];
    __shared__ int carry;
    int t = threadIdx.x;
    if (t == 0) carry = 0;
    __syncthreads();
    for (int base = 0; base < n; base += 1024) {
        int i = base + t;
        int orig = (i < n) ? v[i] : 0;
        int x = orig;
        #pragma unroll
        for (int o = 1; o < 32; o <<= 1) {
            int y = __shfl_up_sync(0xffffffffu, x, o);
            if ((t & 31) >= o) x += y;
        }
        if ((t & 31) == 31) wsum[t >> 5] = x;
        __syncthreads();
        if (t < 32) {
            int w = wsum[t];
            #pragma unroll
            for (int o = 1; o < 32; o <<= 1) {
                int y = __shfl_up_sync(0xffffffffu, w, o);
                if (t >= o) w += y;
            }
            wsum[t] = w;
        }
        __syncthreads();
        int woff = (t >= 32) ? wsum[(t >> 5) - 1] : 0;
        int incl = x + woff + carry;
        if (i < n) offs[i] = incl - orig;
        __syncthreads();
        if (t == 1023) carry = incl;
        __syncthreads();
    }
    if (t == 0) offs[n] = carry;
}
__global__ void k_scan_apply(const int* __restrict__ v, const int* __restrict__ poffs,
                             int* __restrict__ offs, int* __restrict__ cur, int n) {
    __shared__ int wsum[32];
    int t = threadIdx.x;
    int i = blockIdx.x * 1024 + t;
    int orig = (i < n) ? v[i] : 0;
    int x = orig;
    #pragma unroll
    for (int o = 1; o < 32; o <<= 1) {
        int y = __shfl_up_sync(0xffffffffu, x, o);
        if ((t & 31) >= o) x += y;
    }
    if ((t & 31) == 31) wsum[t >> 5] = x;
    __syncthreads();
    if (t < 32) {
        int w = wsum[t];
        #pragma unroll
        for (int o = 1; o < 32; o <<= 1) {
            int y = __shfl_up_sync(0xffffffffu, w, o);
            if (t >= o) w += y;
        }
        wsum[t] = w;
    }
    __syncthreads();
    int woff = (t >= 32) ? wsum[(t >> 5) - 1] : 0;
    int incl = x + woff + poffs[blockIdx.x];
    if (i < n) {
        int ex = incl - orig;
        offs[i] = ex;
        cur[i] = ex;
    }
    if (i == 0) offs[n] = poffs[gridDim.x];
}

__global__ void k_build(const int* __restrict__ dst, const int* __restrict__ src,
                        int* __restrict__ cursor, int* __restrict__ csr, int E) {
    int e = blockIdx.x * blockDim.x + threadIdx.x;
    if (e < E) {
        int p = atomicAdd(&cursor[dst[e]], 1);
        csr[p] = src[e];
    }
}
__global__ void k_init_test(const float* __restrict__ temb, float* __restrict__ h) {
    int i = blockIdx.x * blockDim.x + threadIdx.x;
    if (i < N_TEST * HD) h[i] = temb[i & 127];
}

__global__ void k_split_w(const float* __restrict__ W,
                          __nv_bfloat16* __restrict__ Wh, __nv_bfloat16* __restrict__ Wl) {
    int i = blockIdx.x * blockDim.x + threadIdx.x;
    if (i >= NLAYERS * 16384) return;
    int l = i >> 14, r = i & 16383;
    int k = r >> 7, n = r & 127;
    float w = W[l * 16384 + k * 128 + n];
    __nv_bfloat16 h = __float2bfloat16_rn(w);
    __nv_bfloat16 lo = __float2bfloat16_rn(w - __bfloat162float(h));
    Wh[l * 16384 + n * 128 + k] = h;
    Wl[l * 16384 + n * 128 + k] = lo;
}

__global__ void k_split_wc(const float* __restrict__ Wc,
                           __nv_bfloat16* __restrict__ Wh, __nv_bfloat16* __restrict__ Wl) {
    int i = blockIdx.x * blockDim.x + threadIdx.x;
    if (i >= 16384) return;
    int k = i >> 6, n = i & 63;
    float w = Wc[i];
    __nv_bfloat16 h = __float2bfloat16_rn(w);
    __nv_bfloat16 lo = __float2bfloat16_rn(w - __bfloat162float(h));
    Wh[n * 256 + k] = h;
    Wl[n * 256 + k] = lo;
}

// ---------------- MMA primitive ----------------------------------------------
#define APAD 136
__device__ __forceinline__ void mma16816(float c[4], const uint32_t a[4],
                                         uint32_t b0, uint32_t b1) {
    asm volatile(
        "mma.sync.aligned.m16n8k16.row.col.f32.bf16.bf16.f32 "
        "{%0,%1,%2,%3},{%4,%5,%6,%7},{%8,%9},{%0,%1,%2,%3};"
        : "+f"(c[0]), "+f"(c[1]), "+f"(c[2]), "+f"(c[3])
        : "r"(a[0]), "r"(a[1]), "r"(a[2]), "r"(a[3]), "r"(b0), "r"(b1));
}
__device__ __forceinline__ void split2(float2 x, uint32_t& hi, uint32_t& lo) {
    __nv_bfloat16 h0 = __float2bfloat16_rn(x.x);
    __nv_bfloat16 h1 = __float2bfloat16_rn(x.y);
    __nv_bfloat16 l0 = __float2bfloat16_rn(x.x - __bfloat162float(h0));
    __nv_bfloat16 l1 = __float2bfloat16_rn(x.y - __bfloat162float(h1));
    __nv_bfloat162 hh = __halves2bfloat162(h0, h1);
    __nv_bfloat162 ll = __halves2bfloat162(l0, l1);
    hi = *(uint32_t*)&hh;
    lo = *(uint32_t*)&ll;
}

// ---------------- tensor-core encoder ----------------------------------------
#define EAPAD 260
#define EWPAD 264
#define SM_ENC_A (64 * EWPAD * 2 * 2)
#define SM_ENC_TOT (SM_ENC_A + 32 * EAPAD * 4)

__global__ void __launch_bounds__(256) k_enc_mma(
    const int* __restrict__ label, const float* __restrict__ content,
    const float* __restrict__ emb,
    const __nv_bfloat16* __restrict__ Wch_g, const __nv_bfloat16* __restrict__ Wcl_g,
    const float* __restrict__ bc, float* __restrict__ h)
{
    extern __shared__ __align__(16) char smraw[];
    __nv_bfloat16* Wh = (__nv_bfloat16*)smraw;         // [64][EWPAD]
    __nv_bfloat16* Wl = Wh + 64 * EWPAD;
    float* As = (float*)(smraw + SM_ENC_A);            // [32][EAPAD]
    int t = threadIdx.x;
    int m0 = blockIdx.x * 32;

    #pragma unroll
    for (int j = 0; j < 8; j++) {
        int i = t + 256 * j;
        int nrow = i >> 5, kg = i & 31;
        *(uint4*)&Wh[nrow * EWPAD + kg * 8] = ((const uint4*)Wch_g)[i];
        *(uint4*)&Wl[nrow * EWPAD + kg * 8] = ((const uint4*)Wcl_g)[i];
    }
    #pragma unroll
    for (int j = 0; j < 8; j++) {
        int i = t + 256 * j;
        int r = i >> 6, cg = i & 63;
        *(float4*)&As[r * EAPAD + cg * 4] =
            ((const float4*)content)[(size_t)(m0 + r) * 64 + cg];
    }
    __syncthreads();

    int warp = t >> 5, lane = t & 31;
    int wm = warp & 1, wn = warp >> 1;
    int q = lane & 3, rr = lane >> 2;

    float c[2][4];
    #pragma unroll
    for (int j = 0; j < 2; j++)
        c[j][0] = c[j][1] = c[j][2] = c[j][3] = 0.f;

    #pragma unroll 4
    for (int ks = 0; ks < 16; ks++) {
        int kb = ks * 16;
        const float* ap = &As[(wm * 16 + rr) * EAPAD + kb + q * 2];
        float2 x0 = *(const float2*)(ap);
        float2 x1 = *(const float2*)(ap + 8 * EAPAD);
        float2 x2 = *(const float2*)(ap + 8);
        float2 x3 = *(const float2*)(ap + 8 * EAPAD + 8);
        uint32_t ah[4], al[4];
        split2(x0, ah[0], al[0]);
        split2(x1, ah[1], al[1]);
        split2(x2, ah[2], al[2]);
        split2(x3, ah[3], al[3]);
        #pragma unroll
        for (int nt = 0; nt < 2; nt++) {
            const __nv_bfloat16* bph = Wh + (wn * 16 + nt * 8 + rr) * EWPAD + kb + q * 2;
            const __nv_bfloat16* bpl = Wl + (wn * 16 + nt * 8 + rr) * EWPAD + kb + q * 2;
            uint32_t bh0 = *(const uint32_t*)bph;
            uint32_t bh1 = *(const uint32_t*)(bph + 8);
            uint32_t bl0 = *(const uint32_t*)bpl;
            uint32_t bl1 = *(const uint32_t*)(bpl + 8);
            mma16816(c[nt], ah, bh0, bh1);
            mma16816(c[nt], ah, bl0, bl1);
            mma16816(c[nt], al, bh0, bh1);
        }
    }

    #pragma unroll
    for (int nt = 0; nt < 2; nt++) {
        #pragma unroll
        for (int half = 0; half < 2; half++) {
            int row = m0 + wm * 16 + half * 8 + rr;
            int col = wn * 16 + nt * 8 + q * 2;
            float2 bb = *(const float2*)&bc[col];
            float2 v = make_float2(c[nt][half * 2] + bb.x, c[nt][half * 2 + 1] + bb.y);
            *(float2*)&h[(size_t)row * HD + 64 + col] = v;
        }
    }
    for (int i = t; i < 32 * 64; i += 256) {
        int r = i >> 6, col = i & 63;
        int gn = m0 + r;
        h[(size_t)gn * HD + col] = emb[(size_t)label[gn] * 64 + col];
    }
}

// ---------------- tensor-core GEMM (64-row tile, pre-split bf16 inputs) ------
__global__ void __launch_bounds__(256) k_gemm_mma64(
    const __nv_bfloat16* __restrict__ Ah_g, const __nv_bfloat16* __restrict__ Al_g,
    const __nv_bfloat16* __restrict__ Wh_g, const __nv_bfloat16* __restrict__ Wl_g,
    const float* __restrict__ AddIn, const float* __restrict__ bias,
    const float* __restrict__ res, float* __restrict__ out, int M, int addres, int tile0)
{
    extern __shared__ __align__(16) char smraw[];
    __nv_bfloat16* Ah = (__nv_bfloat16*)smraw;
    __nv_bfloat16* Al = Ah + 64 * APAD;
    __nv_bfloat16* Wh = Al + 64 * APAD;
    __nv_bfloat16* Wl = Wh + 128 * APAD;
    int t = threadIdx.x;
    int m0 = (blockIdx.x + tile0) * 64;

    #pragma unroll
    for (int j = 0; j < 8; j++) {
        int i = t + 256 * j;
        int nrow = i >> 4, kg = i & 15;
        *(uint4*)&Wh[nrow * APAD + kg * 8] = ((const uint4*)Wh_g)[i];
        *(uint4*)&Wl[nrow * APAD + kg * 8] = ((const uint4*)Wl_g)[i];
    }
    #pragma unroll
    for (int j = 0; j < 4; j++) {
        int i = t + 256 * j;
        int r = i >> 4, kg = i & 15;
        long gr = m0 + r;
        uint4 vh = make_uint4(0u, 0u, 0u, 0u), vl = vh;
        if (gr < M) {
            vh = ((const uint4*)Ah_g)[gr * 16 + kg];
            vl = ((const uint4*)Al_g)[gr * 16 + kg];
        }
        *(uint4*)&Ah[r * APAD + kg * 8] = vh;
        *(uint4*)&Al[r * APAD + kg * 8] = vl;
    }
    __syncthreads();

    int warp = t >> 5, lane = t & 31;
    int wm = warp & 1, wn = warp >> 1;
    int q = lane & 3, rr = lane >> 2;

    float c[2][4][4];
    #pragma unroll
    for (int i = 0; i < 2; i++)
        #pragma unroll
        for (int j = 0; j < 4; j++)
            c[i][j][0] = c[i][j][1] = c[i][j][2] = c[i][j][3] = 0.f;

    #pragma unroll
    for (int term = 0; term < 3; term++) {
        const __nv_bfloat16* Ab = (term == 2) ? Al : Ah;
        const __nv_bfloat16* Bb = (term == 1) ? Wl : Wh;
        #pragma unroll
        for (int ks = 0; ks < 8; ks++) {
            int kb = ks * 16;
            uint32_t a[2][4];
            #pragma unroll
            for (int mt = 0; mt < 2; mt++) {
                const __nv_bfloat16* ap = Ab + (wm * 32 + mt * 16 + rr) * APAD + kb + q * 2;
                a[mt][0] = *(const uint32_t*)(ap);
                a[mt][1] = *(const uint32_t*)(ap + 8 * APAD);
                a[mt][2] = *(const uint32_t*)(ap + 8);
                a[mt][3] = *(const uint32_t*)(ap + 8 * APAD + 8);
            }
            #pragma unroll
            for (int nt = 0; nt < 4; nt++) {
                const __nv_bfloat16* bp = Bb + (wn * 32 + nt * 8 + rr) * APAD + kb + q * 2;
                uint32_t b0 = *(const uint32_t*)bp;
                uint32_t b1 = *(const uint32_t*)(bp + 8);
                mma16816(c[0][nt], a[0], b0, b1);
                mma16816(c[1][nt], a[1], b0, b1);
            }
        }
    }

    #pragma unroll
    for (int mt = 0; mt < 2; mt++) {
        #pragma unroll
        for (int half = 0; half < 2; half++) {
            int row = m0 + wm * 32 + mt * 16 + half * 8 + rr;
            if (row >= M) continue;
            #pragma unroll
            for (int nt = 0; nt < 4; nt++) {
                int col = wn * 32 + nt * 8 + q * 2;
                size_t o = (size_t)row * HD + col;
                float2 v = make_float2(c[mt][nt][half * 2], c[mt][nt][half * 2 + 1]);
                float2 d = *(const float2*)&AddIn[o];
                float2 bb = *(const float2*)&bias[col];
                v.x += d.x + bb.x;
                v.y += d.y + bb.y;
                v.x = fmaxf(v.x, 0.f);
                v.y = fmaxf(v.y, 0.f);
                if (addres) {
                    float2 rv = *(const float2*)&res[o];
                    v.x += rv.x; v.y += rv.y;
                }
                *(float2*)&out[o] = v;
            }
        }
    }
}

// ---------------- last-layer variant: MMA + fused decode ---------------------
__global__ void __launch_bounds__(256) k_gemm_mma64_dec(
    const __nv_bfloat16* __restrict__ Ah_g, const __nv_bfloat16* __restrict__ Al_g,
    const __nv_bfloat16* __restrict__ Wh_g, const __nv_bfloat16* __restrict__ Wl_g,
    const float* __restrict__ AddIn, const float* __restrict__ bias,
    const float* __restrict__ dW, const float* __restrict__ db,
    float* __restrict__ logits, float* __restrict__ pred, int write_pred, int tile0)
{
    extern __shared__ __align__(16) char smraw[];
    __nv_bfloat16* Ah = (__nv_bfloat16*)smraw;
    __nv_bfloat16* Al = Ah + 64 * APAD;
    __nv_bfloat16* Wh = Al + 64 * APAD;
    __nv_bfloat16* Wl = Wh + 128 * APAD;
    int t = threadIdx.x;
    int m0 = (blockIdx.x + tile0) * 64;

    #pragma unroll
    for (int j = 0; j < 8; j++) {
        int i = t + 256 * j;
        int nrow = i >> 4, kg = i & 15;
        *(uint4*)&Wh[nrow * APAD + kg * 8] = ((const uint4*)Wh_g)[i];
        *(uint4*)&Wl[nrow * APAD + kg * 8] = ((const uint4*)Wl_g)[i];
    }
    #pragma unroll
    for (int j = 0; j < 4; j++) {
        int i = t + 256 * j;
        int r = i >> 4, kg = i & 15;
        long gr = m0 + r;
        *(uint4*)&Ah[r * APAD + kg * 8] = ((const uint4*)Ah_g)[gr * 16 + kg];
        *(uint4*)&Al[r * APAD + kg * 8] = ((const uint4*)Al_g)[gr * 16 + kg];
    }
    __syncthreads();

    int warp = t >> 5, lane = t & 31;
    int wm = warp & 1, wn = warp >> 1;
    int q = lane & 3, rr = lane >> 2;

    float c[2][4][4];
    #pragma unroll
    for (int i = 0; i < 2; i++)
        #pragma unroll
        for (int j = 0; j < 4; j++)
            c[i][j][0] = c[i][j][1] = c[i][j][2] = c[i][j][3] = 0.f;

    #pragma unroll
    for (int term = 0; term < 3; term++) {
        const __nv_bfloat16* Ab = (term == 2) ? Al : Ah;
        const __nv_bfloat16* Bb = (term == 1) ? Wl : Wh;
        #pragma unroll
        for (int ks = 0; ks < 8; ks++) {
            int kb = ks * 16;
            uint32_t a[2][4];
            #pragma unroll
            for (int mt = 0; mt < 2; mt++) {
                const __nv_bfloat16* ap = Ab + (wm * 32 + mt * 16 + rr) * APAD + kb + q * 2;
                a[mt][0] = *(const uint32_t*)(ap);
                a[mt][1] = *(const uint32_t*)(ap + 8 * APAD);
                a[mt][2] = *(const uint32_t*)(ap + 8);
                a[mt][3] = *(const uint32_t*)(ap + 8 * APAD + 8);
            }
            #pragma unroll
            for (int nt = 0; nt < 4; nt++) {
                const __nv_bfloat16* bp = Bb + (wn * 32 + nt * 8 + rr) * APAD + kb + q * 2;
                uint32_t b0 = *(const uint32_t*)bp;
                uint32_t b1 = *(const uint32_t*)(bp + 8);
                mma16816(c[0][nt], a[0], b0, b1);
                mma16816(c[1][nt], a[1], b0, b1);
            }
        }
    }

    float l0[4] = {0.f, 0.f, 0.f, 0.f};
    float l1[4] = {0.f, 0.f, 0.f, 0.f};
    #pragma unroll
    for (int mt = 0; mt < 2; mt++) {
        #pragma unroll
        for (int half = 0; half < 2; half++) {
            int row = m0 + wm * 32 + mt * 16 + half * 8 + rr;
            int ridx = mt * 2 + half;
            #pragma unroll
            for (int nt = 0; nt < 4; nt++) {
                int col = wn * 32 + nt * 8 + q * 2;
                size_t o = (size_t)row * HD + col;
                float2 v = make_float2(c[mt][nt][half * 2], c[mt][nt][half * 2 + 1]);
                float2 d = *(const float2*)&AddIn[o];
                float2 bb = *(const float2*)&bias[col];
                v.x = fmaxf(v.x + d.x + bb.x, 0.f);
                v.y = fmaxf(v.y + d.y + bb.y, 0.f);
                float2 w0 = *(const float2*)&dW[col * 2];
                float2 w1 = *(const float2*)&dW[(col + 1) * 2];
                l0[ridx] += v.x * w0.x + v.y * w1.x;
                l1[ridx] += v.x * w0.y + v.y * w1.y;
            }
        }
    }
    #pragma unroll
    for (int ridx = 0; ridx < 4; ridx++) {
        l0[ridx] += __shfl_xor_sync(0xffffffffu, l0[ridx], 1);
        l0[ridx] += __shfl_xor_sync(0xffffffffu, l0[ridx], 2);
        l1[ridx] += __shfl_xor_sync(0xffffffffu, l1[ridx], 1);
        l1[ridx] += __shfl_xor_sync(0xffffffffu, l1[ridx], 2);
    }
    __syncthreads();
    float* dsm = (float*)smraw;
    if (q == 0) {
        #pragma unroll
        for (int mt = 0; mt < 2; mt++) {
            #pragma unroll
            for (int half = 0; half < 2; half++) {
                int rloc = wm * 32 + mt * 16 + half * 8 + rr;
                int ridx = mt * 2 + half;
                dsm[rloc * 8 + wn * 2 + 0] = l0[ridx];
                dsm[rloc * 8 + wn * 2 + 1] = l1[ridx];
            }
        }
    }
    __syncthreads();
    if (t < 64) {
        float L0 = dsm[t * 8] + dsm[t * 8 + 2] + dsm[t * 8 + 4] + dsm[t * 8 + 6] + db[0];
        float L1 = dsm[t * 8 + 1] + dsm[t * 8 + 3] + dsm[t * 8 + 5] + dsm[t * 8 + 7] + db[1];
        long grow = m0 + t;
        logits[grow * 2]     = L0;
        logits[grow * 2 + 1] = L1;
        if (write_pred) {
            float mx = fmaxf(L0, L1);
            float e0 = expf(L0 - mx), e1 = expf(L1 - mx);
            float s = e0 + e1;
            pred[grow * 2]     = e0 / s;
            pred[grow * 2 + 1] = e1 / s;
        }
    }
}

// ---------------- FFMA GEMM with fused epilogue (small M) -------------------
__global__ void __launch_bounds__(256) k_gemm_ep(
    const float* __restrict__ A, const float* __restrict__ W,
    const float* __restrict__ AddIn, const float* __restrict__ bias,
    const float* __restrict__ res, float* __restrict__ out, int M, int flags)
{
    extern __shared__ float sm[];
    float* Ws = sm;
    float* As = sm + 16384;
    int t = threadIdx.x;
    const float4* W4 = (const float4*)W;
    float4* Ws4 = (float4*)Ws;
    #pragma unroll
    for (int i = 0; i < 16; i++) Ws4[t + 256 * i] = W4[t + 256 * i];
    int m0 = blockIdx.x * 64;
    #pragma unroll
    for (int i = 0; i < 8; i++) {
        int idx = t + 256 * i;
        int r = idx >> 5, cc = idx & 31;
        int gr = m0 + r;
        float4 v = (gr < M) ? ((const float4*)A)[(size_t)gr * 32 + cc]
                            : make_float4(0.f, 0.f, 0.f, 0.f);
        *(float4*)&As[r * 132 + cc * 4] = v;
    }
    __syncthreads();
    int c0 = (t & 31) * 4;
    int r0 = (t >> 5) * 8;
    float acc[8][4];
    #pragma unroll
    for (int i = 0; i < 8; i++) { acc[i][0] = acc[i][1] = acc[i][2] = acc[i][3] = 0.f; }
    #pragma unroll 2
    for (int k = 0; k < 128; k++) {
        float4 w = *(const float4*)&Ws[k * 128 + c0];
        #pragma unroll
        for (int i = 0; i < 8; i++) {
            float a = As[(r0 + i) * 132 + k];
            acc[i][0] += a * w.x;
            acc[i][1] += a * w.y;
            acc[i][2] += a * w.z;
            acc[i][3] += a * w.w;
        }
    }
    float4 bb = make_float4(0.f, 0.f, 0.f, 0.f);
    if (flags & F_BIAS) bb = *(const float4*)&bias[c0];
    #pragma unroll
    for (int i = 0; i < 8; i++) {
        int gr = m0 + r0 + i;
        if (gr < M) {
            size_t o = (size_t)gr * HD + c0;
            float4 v = make_float4(acc[i][0] + bb.x, acc[i][1] + bb.y,
                                   acc[i][2] + bb.z, acc[i][3] + bb.w);
            if (flags & F_ADDIN) {
                float4 d = *(const float4*)&AddIn[o];
                v.x += d.x; v.y += d.y; v.z += d.z; v.w += d.w;
            }
            if (flags & F_RELU) {
                v.x = fmaxf(v.x, 0.f); v.y = fmaxf(v.y, 0.f);
                v.z = fmaxf(v.z, 0.f); v.w = fmaxf(v.w, 0.f);
            }
            if (flags & F_ADDRES) {
                float4 rv = *(const float4*)&res[o];
                v.x += rv.x; v.y += rv.y; v.z += rv.z; v.w += rv.w;
            }
            *(float4*)&out[o] = v;
        }
    }
}

// ---------------- mean aggregation (fp32 out) -------------------------------
__global__ void k_agg(const float* __restrict__ X,
                      const int* __restrict__ offs, const int* __restrict__ csr,
                      float* __restrict__ out, int n)
{
    int node = (blockIdx.x * blockDim.x + threadIdx.x) >> 5;
    if (node >= n) return;
    int lane = threadIdx.x & 31;
    int s0 = offs[node], s1 = offs[node + 1];
    float4 a = make_float4(0.f, 0.f, 0.f, 0.f);
    for (int e0 = s0; e0 < s1; e0 += 32) {
        int idx = (e0 + lane < s1) ? csr[e0 + lane] : 0;
        int m = min(32, s1 - e0);
        #pragma unroll 4
        for (int j = 0; j < m; j++) {
            int s = __shfl_sync(0xffffffffu, idx, j);
            float4 v = *(const float4*)&X[(size_t)s * HD + lane * 4];
            a.x += v.x; a.y += v.y; a.z += v.z; a.w += v.w;
        }
    }
    float inv = 1.f / (float)((s1 - s0) > 0 ? (s1 - s0) : 1);
    *(float4*)&out[(size_t)node * HD + lane * 4] =
        make_float4(a.x * inv, a.y * inv, a.z * inv, a.w * inv);
}

// ---------------- chunked mean aggregation with fused bf16 split output -----
__global__ void k_agg_bf(const float* __restrict__ X,
                         const int* __restrict__ offs, const int* __restrict__ csr,
                         __nv_bfloat16* __restrict__ Sh, __nv_bfloat16* __restrict__ Sl,
                         int n0, int n1)
{
    int node = n0 + ((blockIdx.x * blockDim.x + threadIdx.x) >> 5);
    if (node >= n1) return;
    int lane = threadIdx.x & 31;
    int s0 = offs[node], s1 = offs[node + 1];
    float4 a = make_float4(0.f, 0.f, 0.f, 0.f);
    for (int e0 = s0; e0 < s1; e0 += 32) {
        int idx = (e0 + lane < s1) ? csr[e0 + lane] : 0;
        int m = min(32, s1 - e0);
        #pragma unroll 4
        for (int j = 0; j < m; j++) {
            int s = __shfl_sync(0xffffffffu, idx, j);
            float4 v = *(const float4*)&X[(size_t)s * HD + lane * 4];
            a.x += v.x; a.y += v.y; a.z += v.z; a.w += v.w;
        }
    }
    float inv = 1.f / (float)((s1 - s0) > 0 ? (s1 - s0) : 1);
    const float mv[4] = {a.x * inv, a.y * inv, a.z * inv, a.w * inv};
    __nv_bfloat16 hh[4], ll[4];
    #pragma unroll
    for (int u = 0; u < 4; u++) {
        hh[u] = __float2bfloat16_rn(mv[u]);
        ll[u] = __float2bfloat16_rn(mv[u] - __bfloat162float(hh[u]));
    }
    size_t o = (size_t)node * HD + lane * 4;
    *(uint2*)&Sh[o] = *(uint2*)hh;
    *(uint2*)&Sl[o] = *(uint2*)ll;
}

// ---------------- launch ----------------------------------------------------
extern "C" void kernel_launch(void* const* d_in, const int* in_sizes, int n_in,
                              void* d_out, int out_size)
{
    const int*   ast_label   = (const int*)d_in[0];
    const float* ast_content = (const float*)d_in[1];
    const int* src_aa = (const int*)d_in[2];
    const int* dst_aa = (const int*)d_in[3];
    const int* src_at = (const int*)d_in[4];
    const int* dst_at = (const int*)d_in[5];
    const int* src_ta = (const int*)d_in[6];
    const int* dst_ta = (const int*)d_in[7];
    int E_aa = in_sizes[2], E_at = in_sizes[4], E_ta = in_sizes[6];

    int p = 8;
    if (n_in > 8 && in_sizes[8] == 1) p = 9;
    const float* emb    = (const float*)d_in[p + 0];
    const float* Wc     = (const float*)d_in[p + 1];
    const float* bc     = (const float*)d_in[p + 2];
    const float* temb   = (const float*)d_in[p + 3];
    const float* W_aa   = (const float*)d_in[p + 4];
    const float* W_at   = (const float*)d_in[p + 5];
    const float* W_ta   = (const float*)d_in[p + 6];
    const float* b_ast  = (const float*)d_in[p + 7];
    const float* b_test = (const float*)d_in[p + 8];
    const float* dW     = (const float*)d_in[p + 9];
    const float* db     = (const float*)d_in[p + 10];

    float* F = nullptr;
    int*   I = nullptr;
    cudaGetSymbolAddress((void**)&F, g_f);
    cudaGetSymbolAddress((void**)&I, g_i);

    cudaFuncSetAttribute(k_gemm_ep,        cudaFuncAttributeMaxDynamicSharedMemorySize, 99328);
    cudaFuncSetAttribute(k_gemm_mma64,     cudaFuncAttributeMaxDynamicSharedMemorySize, 104448);
    cudaFuncSetAttribute(k_gemm_mma64_dec, cudaFuncAttributeMaxDynamicSharedMemorySize, 104448);
    cudaFuncSetAttribute(k_enc_mma,        cudaFuncAttributeMaxDynamicSharedMemorySize, SM_ENC_TOT);

    float* hA  = F + F_HA;   float* hB  = F + F_HB;
    __nv_bfloat16* Sh = (__nv_bfloat16*)(F + F_SH);
    __nv_bfloat16* Sl = (__nv_bfloat16*)(F + F_SL);
    float* Mta = F + F_MTA;
    float* Xta = F + F_XTA;  float* St  = F + F_STB;
    float* hTA = F + F_HTA;  float* hTB = F + F_HTB;
    __nv_bfloat16* Whg  = (__nv_bfloat16*)(F + F_WS);
    __nv_bfloat16* Wlg  = (__nv_bfloat16*)(F + F_WS + 40960u);
    __nv_bfloat16* Wchg = (__nv_bfloat16*)(F + F_WC);
    __nv_bfloat16* Wclg = (__nv_bfloat16*)(F + F_WC + 8192u);

    int* off_aa = I + I_OFF_AA; int* off_ta = I + I_OFF_TA; int* off_at = I + I_OFF_AT;
    int* cur_aa = I + I_CUR_AA; int* cur_ta = I + I_CUR_TA; int* cur_at = I + I_CUR_AT;
    int* csr_aa = I + I_CSR_AA; int* csr_ta = I + I_CSR_TA; int* csr_at = I + I_CSR_AT;
    int* part0 = I + I_PART0; int* poff0 = I + I_POFF0;
    int* part1 = I + I_PART1; int* poff1 = I + I_POFF1;
    int* part2 = I + I_PART2; int* poff2 = I + I_POFF2;

    int nb_ast  = div_up(N_AST, 1024);
    int nb_test = div_up(N_TEST, 1024);

    cudaStream_t s0 = 0, s1 = g_sx.s1, s2 = g_sx.s2;
    cudaEvent_t* ev = g_sx.ev;

    // chunk boundaries (in 64-row tiles); 3125 tiles total
    const int NCH = 4;
    const int tb[NCH + 1] = {0, 782, 1564, 2346, 3125};

    cudaEventRecord(ev[EV_ROOT], s0);
    cudaStreamWaitEvent(s1, ev[EV_ROOT], 0);
    cudaStreamWaitEvent(s2, ev[EV_ROOT], 0);

    // --- s0: aa CSR + weight splits + encode ---
    k_zero_int<<<div_up(N_AST, 256), 256, 0, s0>>>(cur_aa, N_AST);
    k_hist<<<div_up(E_aa, 256), 256, 0, s0>>>(dst_aa, cur_aa, E_aa);
    k_blocksum<<<nb_ast, 1024, 0, s0>>>(cur_aa, part0, N_AST);
    k_exscan<<<1, 1024, 0, s0>>>(part0, poff0, nb_ast);
    k_scan_apply<<<nb_ast, 1024, 0, s0>>>(cur_aa, poff0, off_aa, cur_aa, N_AST);
    k_build<<<div_up(E_aa, 256), 256, 0, s0>>>(dst_aa, src_aa, cur_aa, csr_aa, E_aa);
    k_split_w<<<div_up(NLAYERS * 16384, 256), 256, 0, s0>>>(W_aa, Whg, Wlg);
    k_split_wc<<<div_up(16384, 256), 256, 0, s0>>>(Wc, Wchg, Wclg);
    k_enc_mma<<<N_AST / 32, 256, SM_ENC_TOT, s0>>>(ast_label, ast_content, emb,
                                                   Wchg, Wclg, bc, hA);
    cudaEventRecord(ev[EV_ENC], s0);

    // --- s1: ta CSR + init_test ---
    k_zero_int<<<div_up(N_AST, 256), 256, 0, s1>>>(cur_ta, N_AST);
    k_hist<<<div_up(E_ta, 256), 256, 0, s1>>>(dst_ta, cur_ta, E_ta);
    k_blocksum<<<nb_ast, 1024, 0, s1>>>(cur_ta, part1, N_AST);
    k_exscan<<<1, 1024, 0, s1>>>(part1, poff1, nb_ast);
    k_scan_apply<<<nb_ast, 1024, 0, s1>>>(cur_ta, poff1, off_ta, cur_ta, N_AST);
    k_build<<<div_up(E_ta, 256), 256, 0, s1>>>(dst_ta, src_ta, cur_ta, csr_ta, E_ta);
    k_init_test<<<div_up(N_TEST * HD, 256), 256, 0, s1>>>(temb, hTA);
    cudaEventRecord(ev[EV_INITT], s1);
    cudaStreamWaitEvent(s1, ev[EV_ENC], 0);  // covers split_w before first mma64

    // --- s2: at CSR ---
    k_zero_int<<<div_up(N_TEST, 256), 256, 0, s2>>>(cur_at, N_TEST);
    k_hist<<<div_up(E_at, 256), 256, 0, s2>>>(dst_at, cur_at, E_at);
    k_blocksum<<<nb_test, 1024, 0, s2>>>(cur_at, part2, N_TEST);
    k_exscan<<<1, 1024, 0, s2>>>(part2, poff2, nb_test);
    k_scan_apply<<<nb_test, 1024, 0, s2>>>(cur_at, poff2, off_at, cur_at, N_TEST);
    k_build<<<div_up(E_at, 256), 256, 0, s2>>>(dst_at, src_at, cur_at, csr_at, E_at);
    cudaStreamWaitEvent(s2, ev[EV_ENC], 0);
    cudaStreamWaitEvent(s2, ev[EV_INITT], 0);

    float* logits = (float*)d_out;
    int write_pred = (out_size >= 4 * N_AST);
    float* pred = logits + 2 * N_AST;

    // --- 5 GCN layers, chunk-pipelined: s0 gathers, s1 MMA+Mta, s2 test path ---
    const float* ia = hA; const float* it = hTA;
    float* oa = hB; float* ot = hTB;
    for (int l = 0; l < NLAYERS; l++) {
        int add  = (l == 1 || l == 3);
        int last = (l == NLAYERS - 1);

        // s0: big gather in 4 chunks
        if (l > 0) cudaStreamWaitEvent(s0, ev[EV_MMA(l - 1)], 0);
        for (int c = 0; c < NCH; c++) {
            int n0 = tb[c] * 64;
            int n1 = tb[c + 1] * 64; if (n1 > N_AST) n1 = N_AST;
            k_agg_bf<<<div_up((n1 - n0) * 32, 256), 256, 0, s0>>>(
                ia, off_aa, csr_aa, Sh, Sl, n0, n1);
            cudaEventRecord(ev[EV_AGG(l, c)], s0);
        }

        // s2: test-node path (aggSt -> gemmAt)   [dead at last layer]
        if (!last) {
            if (l > 0) cudaStreamWaitEvent(s2, ev[EV_MMA(l - 1)], 0);
            k_agg<<<div_up(N_TEST * 32, 256), 256, 0, s2>>>(ia, off_at, csr_at, St, N_TEST);
            k_gemm_ep<<<div_up(N_TEST, 64), 256, 99328, s2>>>(St, W_at + (size_t)l * HD * HD,
                nullptr, b_test + l * HD, it, ot, N_TEST,
                F_BIAS | F_RELU | (add ? F_ADDRES : 0));
            cudaEventRecord(ev[EV_AT(l)], s2);
        }

        // s1: Mta chain then chunked MMA
        if (l > 0) cudaStreamWaitEvent(s1, ev[EV_AT(l - 1)], 0);
        k_gemm_ep<<<div_up(N_TEST, 64), 256, 99328, s1>>>(it, W_ta + (size_t)l * HD * HD,
            nullptr, nullptr, nullptr, Xta, N_TEST, 0);
        k_agg<<<div_up(N_AST * 32, 256), 256, 0, s1>>>(Xta, off_ta, csr_ta, Mta, N_AST);
        for (int c = 0; c < NCH; c++) {
            cudaStreamWaitEvent(s1, ev[EV_AGG(l, c)], 0);
            int ctiles = tb[c + 1] - tb[c];
            if (!last) {
                k_gemm_mma64<<<ctiles, 256, 104448, s1>>>(Sh, Sl,
                    Whg + (size_t)l * 16384, Wlg + (size_t)l * 16384,
                    Mta, b_ast + l * HD, ia, oa, N_AST, add, tb[c]);
            } else {
                k_gemm_mma64_dec<<<ctiles, 256, 104448, s1>>>(Sh, Sl,
                    Whg + (size_t)l * 16384, Wlg + (size_t)l * 16384,
                    Mta, b_ast + l * HD, dW, db, logits, pred, write_pred, tb[c]);
            }
        }
        cudaEventRecord(ev[last ? EV_FIN : EV_MMA(l)], s1);

        const float* ta = ia; ia = oa; oa = (float*)ta;
        if (!last) { const float* tt = it; it = ot; ot = (float*)tt; }
    }

    // join everything back to the capture-origin stream
    cudaStreamWaitEvent(s0, ev[EV_FIN], 0);
}

// round 14
// speedup vs baseline: 1.0398x; 1.0398x over previous
#include <cuda_runtime.h>
#include <cuda_bf16.h>
#include <cstdint>

#define N_AST   200000
#define N_TEST  10000
#define HD      128
#define NLAYERS 5

// ---------------- scratch (device globals; no allocation allowed) ----------
#define F_HA   0u
#define F_HB   25600000u
#define F_SH   51200000u      // Sh bf16
#define F_SL   64000000u      // Sl bf16
#define F_MTA  76800000u
#define F_XTA  102400000u
#define F_STB  103680000u
#define F_HTA  104960000u
#define F_HTB  106240000u
#define F_WS   107520000u     // Wh/Wl pre-split (81920 floats)
#define F_WC   107601920u     // Wch/Wcl pre-split (16384 floats)
#define F_TOT  107618304u
__device__ float g_f[F_TOT];

#define I_OFF_AA 0
#define I_OFF_TA 200001
#define I_OFF_AT 400002
#define I_CUR_AA 410003
#define I_CUR_TA 610003
#define I_CUR_AT 810003
#define I_CSR_AA 820013
#define I_CSR_TA 2820013
#define I_CSR_AT 3320013
#define I_PART0  3820013
#define I_POFF0  3820813
#define I_PART1  3821614
#define I_POFF1  3822414
#define I_PART2  3823215
#define I_POFF2  3824015
#define I_TOT    3824816
__device__ int g_i[I_TOT];

static inline int div_up(int a, int b) { return (a + b - 1) / b; }

#define F_ADDIN  1
#define F_BIAS   2
#define F_RELU   4
#define F_ADDRES 8

// ---------------- streams/events (static init; not device-memory allocs) ----
#define NEV 20
struct SxInit {
    cudaStream_t s1, s2;
    cudaEvent_t ev[NEV];
    SxInit() {
        s1 = nullptr; s2 = nullptr;
        cudaStreamCreateWithFlags(&s1, cudaStreamNonBlocking);
        cudaStreamCreateWithFlags(&s2, cudaStreamNonBlocking);
        for (int i = 0; i < NEV; i++) {
            ev[i] = nullptr;
            cudaEventCreateWithFlags(&ev[i], cudaEventDisableTiming);
        }
    }
};
static SxInit g_sx;
#define EV_ROOT  0
#define EV_ENC   1
#define EV_INITT 2
#define EV_MMA(l) (3 + (l))    // 3..6 (l=0..3)
#define EV_MTA(l) (7 + (l))    // 7..11
#define EV_AT(l)  (12 + (l))   // 12..15

// ---------------- small utility kernels ------------------------------------
__global__ void k_zero_int(int* __restrict__ p, int n) {
    int i = blockIdx.x * blockDim.x + threadIdx.x;
    if (i < n) p[i] = 0;
}
__global__ void k_hist(const int* __restrict__ dst, int* __restrict__ deg, int E) {
    int e = blockIdx.x * blockDim.x + threadIdx.x;
    if (e < E) atomicAdd(&deg[dst[e]], 1);
}

__global__ void k_blocksum(const int* __restrict__ v, int* __restrict__ part, int n) {
    __shared__ int ws[32];
    int t = threadIdx.x;
    int i = blockIdx.x * 1024 + t;
    int x = (i < n) ? v[i] : 0;
    #pragma unroll
    for (int o = 16; o; o >>= 1) x += __shfl_xor_sync(0xffffffffu, x, o);
    if ((t & 31) == 0) ws[t >> 5] = x;
    __syncthreads();
    if (t < 32) {
        int y = ws[t];
        #pragma unroll
        for (int o = 16; o; o >>= 1) y += __shfl_xor_sync(0xffffffffu, y, o);
        if (t == 0) part[blockIdx.x] = y;
    }
}
__global__ void k_exscan(const int* __restrict__ v, int* __restrict__ offs, int n) {
    __shared__ int wsum[32];
    __shared__ int carry;
    int t = threadIdx.x;
    if (t == 0) carry = 0;
    __syncthreads();
    for (int base = 0; base < n; base += 1024) {
        int i = base + t;
        int orig = (i < n) ? v[i] : 0;
        int x = orig;
        #pragma unroll
        for (int o = 1; o < 32; o <<= 1) {
            int y = __shfl_up_sync(0xffffffffu, x, o);
            if ((t & 31) >= o) x += y;
        }
        if ((t & 31) == 31) wsum[t >> 5] = x;
        __syncthreads();
        if (t < 32) {
            int w = wsum[t];
            #pragma unroll
            for (int o = 1; o < 32; o <<= 1) {
                int y = __shfl_up_sync(0xffffffffu, w, o);
                if (t >= o) w += y;
            }
            wsum[t] = w;
        }
        __syncthreads();
        int woff = (t >= 32) ? wsum[(t >> 5) - 1] : 0;
        int incl = x + woff + carry;
        if (i < n) offs[i] = incl - orig;
        __syncthreads();
        if (t == 1023) carry = incl;
        __syncthreads();
    }
    if (t == 0) offs[n] = carry;
}
__global__ void k_scan_apply(const int* __restrict__ v, const int* __restrict__ poffs,
                             int* __restrict__ offs, int* __restrict__ cur, int n) {
    __shared__ int wsum[32];
    int t = threadIdx.x;
    int i = blockIdx.x * 1024 + t;
    int orig = (i < n) ? v[i] : 0;
    int x = orig;
    #pragma unroll
    for (int o = 1; o < 32; o <<= 1) {
        int y = __shfl_up_sync(0xffffffffu, x, o);
        if ((t & 31) >= o) x += y;
    }
    if ((t & 31) == 31) wsum[t >> 5] = x;
    __syncthreads();
    if (t < 32) {
        int w = wsum[t];
        #pragma unroll
        for (int o = 1; o < 32; o <<= 1) {
            int y = __shfl_up_sync(0xffffffffu, w, o);
            if (t >= o) w += y;
        }
        wsum[t] = w;
    }
    __syncthreads();
    int woff = (t >= 32) ? wsum[(t >> 5) - 1] : 0;
    int incl = x + woff + poffs[blockIdx.x];
    if (i < n) {
        int ex = incl - orig;
        offs[i] = ex;
        cur[i] = ex;
    }
    if (i == 0) offs[n] = poffs[gridDim.x];
}

__global__ void k_build(const int* __restrict__ dst, const int* __restrict__ src,
                        int* __restrict__ cursor, int* __restrict__ csr, int E) {
    int e = blockIdx.x * blockDim.x + threadIdx.x;
    if (e < E) {
        int p = atomicAdd(&cursor[dst[e]], 1);
        csr[p] = src[e];
    }
}
__global__ void k_init_test(const float* __restrict__ temb, float* __restrict__ h) {
    int i = blockIdx.x * blockDim.x + threadIdx.x;
    if (i < N_TEST * HD) h[i] = temb[i & 127];
}

__global__ void k_split_w(const float* __restrict__ W,
                          __nv_bfloat16* __restrict__ Wh, __nv_bfloat16* __restrict__ Wl) {
    int i = blockIdx.x * blockDim.x + threadIdx.x;
    if (i >= NLAYERS * 16384) return;
    int l = i >> 14, r = i & 16383;
    int k = r >> 7, n = r & 127;
    float w = W[l * 16384 + k * 128 + n];
    __nv_bfloat16 h = __float2bfloat16_rn(w);
    __nv_bfloat16 lo = __float2bfloat16_rn(w - __bfloat162float(h));
    Wh[l * 16384 + n * 128 + k] = h;
    Wl[l * 16384 + n * 128 + k] = lo;
}

__global__ void k_split_wc(const float* __restrict__ Wc,
                           __nv_bfloat16* __restrict__ Wh, __nv_bfloat16* __restrict__ Wl) {
    int i = blockIdx.x * blockDim.x + threadIdx.x;
    if (i >= 16384) return;
    int k = i >> 6, n = i & 63;
    float w = Wc[i];
    __nv_bfloat16 h = __float2bfloat16_rn(w);
    __nv_bfloat16 lo = __float2bfloat16_rn(w - __bfloat162float(h));
    Wh[n * 256 + k] = h;
    Wl[n * 256 + k] = lo;
}

// ---------------- MMA primitive ----------------------------------------------
#define APAD 136
__device__ __forceinline__ void mma16816(float c[4], const uint32_t a[4],
                                         uint32_t b0, uint32_t b1) {
    asm volatile(
        "mma.sync.aligned.m16n8k16.row.col.f32.bf16.bf16.f32 "
        "{%0,%1,%2,%3},{%4,%5,%6,%7},{%8,%9},{%0,%1,%2,%3};"
        : "+f"(c[0]), "+f"(c[1]), "+f"(c[2]), "+f"(c[3])
        : "r"(a[0]), "r"(a[1]), "r"(a[2]), "r"(a[3]), "r"(b0), "r"(b1));
}
__device__ __forceinline__ void split2(float2 x, uint32_t& hi, uint32_t& lo) {
    __nv_bfloat16 h0 = __float2bfloat16_rn(x.x);
    __nv_bfloat16 h1 = __float2bfloat16_rn(x.y);
    __nv_bfloat16 l0 = __float2bfloat16_rn(x.x - __bfloat162float(h0));
    __nv_bfloat16 l1 = __float2bfloat16_rn(x.y - __bfloat162float(h1));
    __nv_bfloat162 hh = __halves2bfloat162(h0, h1);
    __nv_bfloat162 ll = __halves2bfloat162(l0, l1);
    hi = *(uint32_t*)&hh;
    lo = *(uint32_t*)&ll;
}

// ---------------- tensor-core encoder ----------------------------------------
#define EAPAD 260
#define EWPAD 264
#define SM_ENC_A (64 * EWPAD * 2 * 2)
#define SM_ENC_TOT (SM_ENC_A + 32 * EAPAD * 4)

__global__ void __launch_bounds__(256) k_enc_mma(
    const int* __restrict__ label, const float* __restrict__ content,
    const float* __restrict__ emb,
    const __nv_bfloat16* __restrict__ Wch_g, const __nv_bfloat16* __restrict__ Wcl_g,
    const float* __restrict__ bc, float* __restrict__ h)
{
    extern __shared__ __align__(16) char smraw[];
    __nv_bfloat16* Wh = (__nv_bfloat16*)smraw;         // [64][EWPAD]
    __nv_bfloat16* Wl = Wh + 64 * EWPAD;
    float* As = (float*)(smraw + SM_ENC_A);            // [32][EAPAD]
    int t = threadIdx.x;
    int m0 = blockIdx.x * 32;

    #pragma unroll
    for (int j = 0; j < 8; j++) {
        int i = t + 256 * j;
        int nrow = i >> 5, kg = i & 31;
        *(uint4*)&Wh[nrow * EWPAD + kg * 8] = ((const uint4*)Wch_g)[i];
        *(uint4*)&Wl[nrow * EWPAD + kg * 8] = ((const uint4*)Wcl_g)[i];
    }
    #pragma unroll
    for (int j = 0; j < 8; j++) {
        int i = t + 256 * j;
        int r = i >> 6, cg = i & 63;
        *(float4*)&As[r * EAPAD + cg * 4] =
            ((const float4*)content)[(size_t)(m0 + r) * 64 + cg];
    }
    __syncthreads();

    int warp = t >> 5, lane = t & 31;
    int wm = warp & 1, wn = warp >> 1;
    int q = lane & 3, rr = lane >> 2;

    float c[2][4];
    #pragma unroll
    for (int j = 0; j < 2; j++)
        c[j][0] = c[j][1] = c[j][2] = c[j][3] = 0.f;

    #pragma unroll 4
    for (int ks = 0; ks < 16; ks++) {
        int kb = ks * 16;
        const float* ap = &As[(wm * 16 + rr) * EAPAD + kb + q * 2];
        float2 x0 = *(const float2*)(ap);
        float2 x1 = *(const float2*)(ap + 8 * EAPAD);
        float2 x2 = *(const float2*)(ap + 8);
        float2 x3 = *(const float2*)(ap + 8 * EAPAD + 8);
        uint32_t ah[4], al[4];
        split2(x0, ah[0], al[0]);
        split2(x1, ah[1], al[1]);
        split2(x2, ah[2], al[2]);
        split2(x3, ah[3], al[3]);
        #pragma unroll
        for (int nt = 0; nt < 2; nt++) {
            const __nv_bfloat16* bph = Wh + (wn * 16 + nt * 8 + rr) * EWPAD + kb + q * 2;
            const __nv_bfloat16* bpl = Wl + (wn * 16 + nt * 8 + rr) * EWPAD + kb + q * 2;
            uint32_t bh0 = *(const uint32_t*)bph;
            uint32_t bh1 = *(const uint32_t*)(bph + 8);
            uint32_t bl0 = *(const uint32_t*)bpl;
            uint32_t bl1 = *(const uint32_t*)(bpl + 8);
            mma16816(c[nt], ah, bh0, bh1);
            mma16816(c[nt], ah, bl0, bl1);
            mma16816(c[nt], al, bh0, bh1);
        }
    }

    #pragma unroll
    for (int nt = 0; nt < 2; nt++) {
        #pragma unroll
        for (int half = 0; half < 2; half++) {
            int row = m0 + wm * 16 + half * 8 + rr;
            int col = wn * 16 + nt * 8 + q * 2;
            float2 bb = *(const float2*)&bc[col];
            float2 v = make_float2(c[nt][half * 2] + bb.x, c[nt][half * 2 + 1] + bb.y);
            *(float2*)&h[(size_t)row * HD + 64 + col] = v;
        }
    }
    for (int i = t; i < 32 * 64; i += 256) {
        int r = i >> 6, col = i & 63;
        int gn = m0 + r;
        h[(size_t)gn * HD + col] = emb[(size_t)label[gn] * 64 + col];
    }
}

// ---------------- tensor-core GEMM (64-row tile, pre-split bf16 inputs) ------
__global__ void __launch_bounds__(256) k_gemm_mma64(
    const __nv_bfloat16* __restrict__ Ah_g, const __nv_bfloat16* __restrict__ Al_g,
    const __nv_bfloat16* __restrict__ Wh_g, const __nv_bfloat16* __restrict__ Wl_g,
    const float* __restrict__ AddIn, const float* __restrict__ bias,
    const float* __restrict__ res, float* __restrict__ out, int M, int addres)
{
    extern __shared__ __align__(16) char smraw[];
    __nv_bfloat16* Ah = (__nv_bfloat16*)smraw;
    __nv_bfloat16* Al = Ah + 64 * APAD;
    __nv_bfloat16* Wh = Al + 64 * APAD;
    __nv_bfloat16* Wl = Wh + 128 * APAD;
    int t = threadIdx.x;
    int m0 = blockIdx.x * 64;

    #pragma unroll
    for (int j = 0; j < 8; j++) {
        int i = t + 256 * j;
        int nrow = i >> 4, kg = i & 15;
        *(uint4*)&Wh[nrow * APAD + kg * 8] = ((const uint4*)Wh_g)[i];
        *(uint4*)&Wl[nrow * APAD + kg * 8] = ((const uint4*)Wl_g)[i];
    }
    #pragma unroll
    for (int j = 0; j < 4; j++) {
        int i = t + 256 * j;
        int r = i >> 4, kg = i & 15;
        long gr = m0 + r;
        uint4 vh = make_uint4(0u, 0u, 0u, 0u), vl = vh;
        if (gr < M) {
            vh = ((const uint4*)Ah_g)[gr * 16 + kg];
            vl = ((const uint4*)Al_g)[gr * 16 + kg];
        }
        *(uint4*)&Ah[r * APAD + kg * 8] = vh;
        *(uint4*)&Al[r * APAD + kg * 8] = vl;
    }
    __syncthreads();

    int warp = t >> 5, lane = t & 31;
    int wm = warp & 1, wn = warp >> 1;
    int q = lane & 3, rr = lane >> 2;

    float c[2][4][4];
    #pragma unroll
    for (int i = 0; i < 2; i++)
        #pragma unroll
        for (int j = 0; j < 4; j++)
            c[i][j][0] = c[i][j][1] = c[i][j][2] = c[i][j][3] = 0.f;

    #pragma unroll
    for (int term = 0; term < 3; term++) {
        const __nv_bfloat16* Ab = (term == 2) ? Al : Ah;
        const __nv_bfloat16* Bb = (term == 1) ? Wl : Wh;
        #pragma unroll
        for (int ks = 0; ks < 8; ks++) {
            int kb = ks * 16;
            uint32_t a[2][4];
            #pragma unroll
            for (int mt = 0; mt < 2; mt++) {
                const __nv_bfloat16* ap = Ab + (wm * 32 + mt * 16 + rr) * APAD + kb + q * 2;
                a[mt][0] = *(const uint32_t*)(ap);
                a[mt][1] = *(const uint32_t*)(ap + 8 * APAD);
                a[mt][2] = *(const uint32_t*)(ap + 8);
                a[mt][3] = *(const uint32_t*)(ap + 8 * APAD + 8);
            }
            #pragma unroll
            for (int nt = 0; nt < 4; nt++) {
                const __nv_bfloat16* bp = Bb + (wn * 32 + nt * 8 + rr) * APAD + kb + q * 2;
                uint32_t b0 = *(const uint32_t*)bp;
                uint32_t b1 = *(const uint32_t*)(bp + 8);
                mma16816(c[0][nt], a[0], b0, b1);
                mma16816(c[1][nt], a[1], b0, b1);
            }
        }
    }

    #pragma unroll
    for (int mt = 0; mt < 2; mt++) {
        #pragma unroll
        for (int half = 0; half < 2; half++) {
            int row = m0 + wm * 32 + mt * 16 + half * 8 + rr;
            if (row >= M) continue;
            #pragma unroll
            for (int nt = 0; nt < 4; nt++) {
                int col = wn * 32 + nt * 8 + q * 2;
                size_t o = (size_t)row * HD + col;
                float2 v = make_float2(c[mt][nt][half * 2], c[mt][nt][half * 2 + 1]);
                float2 d = *(const float2*)&AddIn[o];
                float2 bb = *(const float2*)&bias[col];
                v.x += d.x + bb.x;
                v.y += d.y + bb.y;
                v.x = fmaxf(v.x, 0.f);
                v.y = fmaxf(v.y, 0.f);
                if (addres) {
                    float2 rv = *(const float2*)&res[o];
                    v.x += rv.x; v.y += rv.y;
                }
                *(float2*)&out[o] = v;
            }
        }
    }
}

// ---------------- last-layer variant: MMA + fused decode ---------------------
__global__ void __launch_bounds__(256) k_gemm_mma64_dec(
    const __nv_bfloat16* __restrict__ Ah_g, const __nv_bfloat16* __restrict__ Al_g,
    const __nv_bfloat16* __restrict__ Wh_g, const __nv_bfloat16* __restrict__ Wl_g,
    const float* __restrict__ AddIn, const float* __restrict__ bias,
    const float* __restrict__ dW, const float* __restrict__ db,
    float* __restrict__ logits, float* __restrict__ pred, int write_pred)
{
    extern __shared__ __align__(16) char smraw[];
    __nv_bfloat16* Ah = (__nv_bfloat16*)smraw;
    __nv_bfloat16* Al = Ah + 64 * APAD;
    __nv_bfloat16* Wh = Al + 64 * APAD;
    __nv_bfloat16* Wl = Wh + 128 * APAD;
    int t = threadIdx.x;
    int m0 = blockIdx.x * 64;

    #pragma unroll
    for (int j = 0; j < 8; j++) {
        int i = t + 256 * j;
        int nrow = i >> 4, kg = i & 15;
        *(uint4*)&Wh[nrow * APAD + kg * 8] = ((const uint4*)Wh_g)[i];
        *(uint4*)&Wl[nrow * APAD + kg * 8] = ((const uint4*)Wl_g)[i];
    }
    #pragma unroll
    for (int j = 0; j < 4; j++) {
        int i = t + 256 * j;
        int r = i >> 4, kg = i & 15;
        long gr = m0 + r;
        *(uint4*)&Ah[r * APAD + kg * 8] = ((const uint4*)Ah_g)[gr * 16 + kg];
        *(uint4*)&Al[r * APAD + kg * 8] = ((const uint4*)Al_g)[gr * 16 + kg];
    }
    __syncthreads();

    int warp = t >> 5, lane = t & 31;
    int wm = warp & 1, wn = warp >> 1;
    int q = lane & 3, rr = lane >> 2;

    float c[2][4][4];
    #pragma unroll
    for (int i = 0; i < 2; i++)
        #pragma unroll
        for (int j = 0; j < 4; j++)
            c[i][j][0] = c[i][j][1] = c[i][j][2] = c[i][j][3] = 0.f;

    #pragma unroll
    for (int term = 0; term < 3; term++) {
        const __nv_bfloat16* Ab = (term == 2) ? Al : Ah;
        const __nv_bfloat16* Bb = (term == 1) ? Wl : Wh;
        #pragma unroll
        for (int ks = 0; ks < 8; ks++) {
            int kb = ks * 16;
            uint32_t a[2][4];
            #pragma unroll
            for (int mt = 0; mt < 2; mt++) {
                const __nv_bfloat16* ap = Ab + (wm * 32 + mt * 16 + rr) * APAD + kb + q * 2;
                a[mt][0] = *(const uint32_t*)(ap);
                a[mt][1] = *(const uint32_t*)(ap + 8 * APAD);
                a[mt][2] = *(const uint32_t*)(ap + 8);
                a[mt][3] = *(const uint32_t*)(ap + 8 * APAD + 8);
            }
            #pragma unroll
            for (int nt = 0; nt < 4; nt++) {
                const __nv_bfloat16* bp = Bb + (wn * 32 + nt * 8 + rr) * APAD + kb + q * 2;
                uint32_t b0 = *(const uint32_t*)bp;
                uint32_t b1 = *(const uint32_t*)(bp + 8);
                mma16816(c[0][nt], a[0], b0, b1);
                mma16816(c[1][nt], a[1], b0, b1);
            }
        }
    }

    float l0[4] = {0.f, 0.f, 0.f, 0.f};
    float l1[4] = {0.f, 0.f, 0.f, 0.f};
    #pragma unroll
    for (int mt = 0; mt < 2; mt++) {
        #pragma unroll
        for (int half = 0; half < 2; half++) {
            int row = m0 + wm * 32 + mt * 16 + half * 8 + rr;
            int ridx = mt * 2 + half;
            #pragma unroll
            for (int nt = 0; nt < 4; nt++) {
                int col = wn * 32 + nt * 8 + q * 2;
                size_t o = (size_t)row * HD + col;
                float2 v = make_float2(c[mt][nt][half * 2], c[mt][nt][half * 2 + 1]);
                float2 d = *(const float2*)&AddIn[o];
                float2 bb = *(const float2*)&bias[col];
                v.x = fmaxf(v.x + d.x + bb.x, 0.f);
                v.y = fmaxf(v.y + d.y + bb.y, 0.f);
                float2 w0 = *(const float2*)&dW[col * 2];
                float2 w1 = *(const float2*)&dW[(col + 1) * 2];
                l0[ridx] += v.x * w0.x + v.y * w1.x;
                l1[ridx] += v.x * w0.y + v.y * w1.y;
            }
        }
    }
    #pragma unroll
    for (int ridx = 0; ridx < 4; ridx++) {
        l0[ridx] += __shfl_xor_sync(0xffffffffu, l0[ridx], 1);
        l0[ridx] += __shfl_xor_sync(0xffffffffu, l0[ridx], 2);
        l1[ridx] += __shfl_xor_sync(0xffffffffu, l1[ridx], 1);
        l1[ridx] += __shfl_xor_sync(0xffffffffu, l1[ridx], 2);
    }
    __syncthreads();
    float* dsm = (float*)smraw;
    if (q == 0) {
        #pragma unroll
        for (int mt = 0; mt < 2; mt++) {
            #pragma unroll
            for (int half = 0; half < 2; half++) {
                int rloc = wm * 32 + mt * 16 + half * 8 + rr;
                int ridx = mt * 2 + half;
                dsm[rloc * 8 + wn * 2 + 0] = l0[ridx];
                dsm[rloc * 8 + wn * 2 + 1] = l1[ridx];
            }
        }
    }
    __syncthreads();
    if (t < 64) {
        float L0 = dsm[t * 8] + dsm[t * 8 + 2] + dsm[t * 8 + 4] + dsm[t * 8 + 6] + db[0];
        float L1 = dsm[t * 8 + 1] + dsm[t * 8 + 3] + dsm[t * 8 + 5] + dsm[t * 8 + 7] + db[1];
        long grow = m0 + t;
        logits[grow * 2]     = L0;
        logits[grow * 2 + 1] = L1;
        if (write_pred) {
            float mx = fmaxf(L0, L1);
            float e0 = expf(L0 - mx), e1 = expf(L1 - mx);
            float s = e0 + e1;
            pred[grow * 2]     = e0 / s;
            pred[grow * 2 + 1] = e1 / s;
        }
    }
}

// ---------------- FFMA GEMM with fused epilogue (small M) -------------------
__global__ void __launch_bounds__(256) k_gemm_ep(
    const float* __restrict__ A, const float* __restrict__ W,
    const float* __restrict__ AddIn, const float* __restrict__ bias,
    const float* __restrict__ res, float* __restrict__ out, int M, int flags)
{
    extern __shared__ float sm[];
    float* Ws = sm;
    float* As = sm + 16384;
    int t = threadIdx.x;
    const float4* W4 = (const float4*)W;
    float4* Ws4 = (float4*)Ws;
    #pragma unroll
    for (int i = 0; i < 16; i++) Ws4[t + 256 * i] = W4[t + 256 * i];
    int m0 = blockIdx.x * 64;
    #pragma unroll
    for (int i = 0; i < 8; i++) {
        int idx = t + 256 * i;
        int r = idx >> 5, cc = idx & 31;
        int gr = m0 + r;
        float4 v = (gr < M) ? ((const float4*)A)[(size_t)gr * 32 + cc]
                            : make_float4(0.f, 0.f, 0.f, 0.f);
        *(float4*)&As[r * 132 + cc * 4] = v;
    }
    __syncthreads();
    int c0 = (t & 31) * 4;
    int r0 = (t >> 5) * 8;
    float acc[8][4];
    #pragma unroll
    for (int i = 0; i < 8; i++) { acc[i][0] = acc[i][1] = acc[i][2] = acc[i][3] = 0.f; }
    #pragma unroll 2
    for (int k = 0; k < 128; k++) {
        float4 w = *(const float4*)&Ws[k * 128 + c0];
        #pragma unroll
        for (int i = 0; i < 8; i++) {
            float a = As[(r0 + i) * 132 + k];
            acc[i][0] += a * w.x;
            acc[i][1] += a * w.y;
            acc[i][2] += a * w.z;
            acc[i][3] += a * w.w;
        }
    }
    float4 bb = make_float4(0.f, 0.f, 0.f, 0.f);
    if (flags & F_BIAS) bb = *(const float4*)&bias[c0];
    #pragma unroll
    for (int i = 0; i < 8; i++) {
        int gr = m0 + r0 + i;
        if (gr < M) {
            size_t o = (size_t)gr * HD + c0;
            float4 v = make_float4(acc[i][0] + bb.x, acc[i][1] + bb.y,
                                   acc[i][2] + bb.z, acc[i][3] + bb.w);
            if (flags & F_ADDIN) {
                float4 d = *(const float4*)&AddIn[o];
                v.x += d.x; v.y += d.y; v.z += d.z; v.w += d.w;
            }
            if (flags & F_RELU) {
                v.x = fmaxf(v.x, 0.f); v.y = fmaxf(v.y, 0.f);
                v.z = fmaxf(v.z, 0.f); v.w = fmaxf(v.w, 0.f);
            }
            if (flags & F_ADDRES) {
                float4 rv = *(const float4*)&res[o];
                v.x += rv.x; v.y += rv.y; v.z += rv.z; v.w += rv.w;
            }
            *(float4*)&out[o] = v;
        }
    }
}

// ---------------- mean aggregation (fp32 out) -------------------------------
__global__ void k_agg(const float* __restrict__ X,
                      const int* __restrict__ offs, const int* __restrict__ csr,
                      float* __restrict__ out, int n)
{
    int node = (blockIdx.x * blockDim.x + threadIdx.x) >> 5;
    if (node >= n) return;
    int lane = threadIdx.x & 31;
    int s0 = offs[node], s1 = offs[node + 1];
    float4 a = make_float4(0.f, 0.f, 0.f, 0.f);
    for (int e0 = s0; e0 < s1; e0 += 32) {
        int idx = (e0 + lane < s1) ? csr[e0 + lane] : 0;
        int m = min(32, s1 - e0);
        #pragma unroll 8
        for (int j = 0; j < m; j++) {
            int s = __shfl_sync(0xffffffffu, idx, j);
            float4 v = *(const float4*)&X[(size_t)s * HD + lane * 4];
            a.x += v.x; a.y += v.y; a.z += v.z; a.w += v.w;
        }
    }
    float inv = 1.f / (float)((s1 - s0) > 0 ? (s1 - s0) : 1);
    *(float4*)&out[(size_t)node * HD + lane * 4] =
        make_float4(a.x * inv, a.y * inv, a.z * inv, a.w * inv);
}

// ---------------- mean aggregation with fused bf16 hi/lo split output -------
__global__ void k_agg_bf(const float* __restrict__ X,
                         const int* __restrict__ offs, const int* __restrict__ csr,
                         __nv_bfloat16* __restrict__ Sh, __nv_bfloat16* __restrict__ Sl,
                         int n)
{
    int node = (blockIdx.x * blockDim.x + threadIdx.x) >> 5;
    if (node >= n) return;
    int lane = threadIdx.x & 31;
    int s0 = offs[node], s1 = offs[node + 1];
    float4 a = make_float4(0.f, 0.f, 0.f, 0.f);
    for (int e0 = s0; e0 < s1; e0 += 32) {
        int idx = (e0 + lane < s1) ? csr[e0 + lane] : 0;
        int m = min(32, s1 - e0);
        #pragma unroll 8
        for (int j = 0; j < m; j++) {
            int s = __shfl_sync(0xffffffffu, idx, j);
            float4 v = *(const float4*)&X[(size_t)s * HD + lane * 4];
            a.x += v.x; a.y += v.y; a.z += v.z; a.w += v.w;
        }
    }
    float inv = 1.f / (float)((s1 - s0) > 0 ? (s1 - s0) : 1);
    const float mv[4] = {a.x * inv, a.y * inv, a.z * inv, a.w * inv};
    __nv_bfloat16 hh[4], ll[4];
    #pragma unroll
    for (int u = 0; u < 4; u++) {
        hh[u] = __float2bfloat16_rn(mv[u]);
        ll[u] = __float2bfloat16_rn(mv[u] - __bfloat162float(hh[u]));
    }
    size_t o = (size_t)node * HD + lane * 4;
    *(uint2*)&Sh[o] = *(uint2*)hh;
    *(uint2*)&Sl[o] = *(uint2*)ll;
}

// ---------------- launch ----------------------------------------------------
extern "C" void kernel_launch(void* const* d_in, const int* in_sizes, int n_in,
                              void* d_out, int out_size)
{
    const int*   ast_label   = (const int*)d_in[0];
    const float* ast_content = (const float*)d_in[1];
    const int* src_aa = (const int*)d_in[2];
    const int* dst_aa = (const int*)d_in[3];
    const int* src_at = (const int*)d_in[4];
    const int* dst_at = (const int*)d_in[5];
    const int* src_ta = (const int*)d_in[6];
    const int* dst_ta = (const int*)d_in[7];
    int E_aa = in_sizes[2], E_at = in_sizes[4], E_ta = in_sizes[6];

    int p = 8;
    if (n_in > 8 && in_sizes[8] == 1) p = 9;
    const float* emb    = (const float*)d_in[p + 0];
    const float* Wc     = (const float*)d_in[p + 1];
    const float* bc     = (const float*)d_in[p + 2];
    const float* temb   = (const float*)d_in[p + 3];
    const float* W_aa   = (const float*)d_in[p + 4];
    const float* W_at   = (const float*)d_in[p + 5];
    const float* W_ta   = (const float*)d_in[p + 6];
    const float* b_ast  = (const float*)d_in[p + 7];
    const float* b_test = (const float*)d_in[p + 8];
    const float* dW     = (const float*)d_in[p + 9];
    const float* db     = (const float*)d_in[p + 10];

    float* F = nullptr;
    int*   I = nullptr;
    cudaGetSymbolAddress((void**)&F, g_f);
    cudaGetSymbolAddress((void**)&I, g_i);

    cudaFuncSetAttribute(k_gemm_ep,        cudaFuncAttributeMaxDynamicSharedMemorySize, 99328);
    cudaFuncSetAttribute(k_gemm_mma64,     cudaFuncAttributeMaxDynamicSharedMemorySize, 104448);
    cudaFuncSetAttribute(k_gemm_mma64_dec, cudaFuncAttributeMaxDynamicSharedMemorySize, 104448);
    cudaFuncSetAttribute(k_enc_mma,        cudaFuncAttributeMaxDynamicSharedMemorySize, SM_ENC_TOT);

    float* hA  = F + F_HA;   float* hB  = F + F_HB;
    __nv_bfloat16* Sh = (__nv_bfloat16*)(F + F_SH);
    __nv_bfloat16* Sl = (__nv_bfloat16*)(F + F_SL);
    float* Mta = F + F_MTA;
    float* Xta = F + F_XTA;  float* St  = F + F_STB;
    float* hTA = F + F_HTA;  float* hTB = F + F_HTB;
    __nv_bfloat16* Whg  = (__nv_bfloat16*)(F + F_WS);
    __nv_bfloat16* Wlg  = (__nv_bfloat16*)(F + F_WS + 40960u);
    __nv_bfloat16* Wchg = (__nv_bfloat16*)(F + F_WC);
    __nv_bfloat16* Wclg = (__nv_bfloat16*)(F + F_WC + 8192u);

    int* off_aa = I + I_OFF_AA; int* off_ta = I + I_OFF_TA; int* off_at = I + I_OFF_AT;
    int* cur_aa = I + I_CUR_AA; int* cur_ta = I + I_CUR_TA; int* cur_at = I + I_CUR_AT;
    int* csr_aa = I + I_CSR_AA; int* csr_ta = I + I_CSR_TA; int* csr_at = I + I_CSR_AT;
    int* part0 = I + I_PART0; int* poff0 = I + I_POFF0;
    int* part1 = I + I_PART1; int* poff1 = I + I_POFF1;
    int* part2 = I + I_PART2; int* poff2 = I + I_POFF2;

    int nb_ast  = div_up(N_AST, 1024);
    int nb_test = div_up(N_TEST, 1024);

    cudaStream_t s0 = 0, s1 = g_sx.s1, s2 = g_sx.s2;
    cudaEvent_t* ev = g_sx.ev;

    cudaEventRecord(ev[EV_ROOT], s0);
    cudaStreamWaitEvent(s1, ev[EV_ROOT], 0);
    cudaStreamWaitEvent(s2, ev[EV_ROOT], 0);

    // --- s0: aa CSR + split_wc + encode + split_w ---
    k_zero_int<<<div_up(N_AST, 256), 256, 0, s0>>>(cur_aa, N_AST);
    k_hist<<<div_up(E_aa, 256), 256, 0, s0>>>(dst_aa, cur_aa, E_aa);
    k_blocksum<<<nb_ast, 1024, 0, s0>>>(cur_aa, part0, N_AST);
    k_exscan<<<1, 1024, 0, s0>>>(part0, poff0, nb_ast);
    k_scan_apply<<<nb_ast, 1024, 0, s0>>>(cur_aa, poff0, off_aa, cur_aa, N_AST);
    k_build<<<div_up(E_aa, 256), 256, 0, s0>>>(dst_aa, src_aa, cur_aa, csr_aa, E_aa);
    k_split_wc<<<div_up(16384, 256), 256, 0, s0>>>(Wc, Wchg, Wclg);
    k_enc_mma<<<N_AST / 32, 256, SM_ENC_TOT, s0>>>(ast_label, ast_content, emb,
                                                   Wchg, Wclg, bc, hA);
    cudaEventRecord(ev[EV_ENC], s0);
    k_split_w<<<div_up(NLAYERS * 16384, 256), 256, 0, s0>>>(W_aa, Whg, Wlg);

    // --- s1: ta CSR + init_test ---
    k_zero_int<<<div_up(N_AST, 256), 256, 0, s1>>>(cur_ta, N_AST);
    k_hist<<<div_up(E_ta, 256), 256, 0, s1>>>(dst_ta, cur_ta, E_ta);
    k_blocksum<<<nb_ast, 1024, 0, s1>>>(cur_ta, part1, N_AST);
    k_exscan<<<1, 1024, 0, s1>>>(part1, poff1, nb_ast);
    k_scan_apply<<<nb_ast, 1024, 0, s1>>>(cur_ta, poff1, off_ta, cur_ta, N_AST);
    k_build<<<div_up(E_ta, 256), 256, 0, s1>>>(dst_ta, src_ta, cur_ta, csr_ta, E_ta);
    k_init_test<<<div_up(N_TEST * HD, 256), 256, 0, s1>>>(temb, hTA);
    cudaEventRecord(ev[EV_INITT], s1);

    // --- s2: at CSR ---
    k_zero_int<<<div_up(N_TEST, 256), 256, 0, s2>>>(cur_at, N_TEST);
    k_hist<<<div_up(E_at, 256), 256, 0, s2>>>(dst_at, cur_at, E_at);
    k_blocksum<<<nb_test, 1024, 0, s2>>>(cur_at, part2, N_TEST);
    k_exscan<<<1, 1024, 0, s2>>>(part2, poff2, nb_test);
    k_scan_apply<<<nb_test, 1024, 0, s2>>>(cur_at, poff2, off_at, cur_at, N_TEST);
    k_build<<<div_up(E_at, 256), 256, 0, s2>>>(dst_at, src_at, cur_at, csr_at, E_at);
    cudaStreamWaitEvent(s2, ev[EV_ENC], 0);
    cudaStreamWaitEvent(s2, ev[EV_INITT], 0);

    float* logits = (float*)d_out;
    int write_pred = (out_size >= 4 * N_AST);
    float* pred = logits + 2 * N_AST;

    // --- 5 GCN layers, 3-stream pipeline ---
    const float* ia = hA; const float* it = hTA;
    float* oa = hB; float* ot = hTB;
    for (int l = 0; l < NLAYERS; l++) {
        int add  = (l == 1 || l == 3);
        int last = (l == NLAYERS - 1);

        // s2: test-node path (aggSt -> gemmAt)   [dead at last layer]
        if (!last) {
            if (l > 0) cudaStreamWaitEvent(s2, ev[EV_MMA(l - 1)], 0);
            k_agg<<<div_up(N_TEST * 32, 256), 256, 0, s2>>>(ia, off_at, csr_at, St, N_TEST);
            k_gemm_ep<<<div_up(N_TEST, 64), 256, 99328, s2>>>(St, W_at + (size_t)l * HD * HD,
                nullptr, b_test + l * HD, it, ot, N_TEST,
                F_BIAS | F_RELU | (add ? F_ADDRES : 0));
            cudaEventRecord(ev[EV_AT(l)], s2);
        }

        // s1: Mta chain (gemmXta -> aggMta)
        if (l > 0) cudaStreamWaitEvent(s1, ev[EV_AT(l - 1)], 0);
        k_gemm_ep<<<div_up(N_TEST, 64), 256, 99328, s1>>>(it, W_ta + (size_t)l * HD * HD,
            nullptr, nullptr, nullptr, Xta, N_TEST, 0);
        if (l > 0) cudaStreamWaitEvent(s1, ev[EV_MMA(l - 1)], 0);
        k_agg<<<div_up(N_AST * 32, 256), 256, 0, s1>>>(Xta, off_ta, csr_ta, Mta, N_AST);
        cudaEventRecord(ev[EV_MTA(l)], s1);

        // s0: big gather + tensor-core GEMM
        k_agg_bf<<<div_up(N_AST * 32, 256), 256, 0, s0>>>(ia, off_aa, csr_aa, Sh, Sl, N_AST);
        cudaStreamWaitEvent(s0, ev[EV_MTA(l)], 0);
        if (!last) {
            k_gemm_mma64<<<div_up(N_AST, 64), 256, 104448, s0>>>(Sh, Sl,
                Whg + (size_t)l * 16384, Wlg + (size_t)l * 16384,
                Mta, b_ast + l * HD, ia, oa, N_AST, add);
            cudaEventRecord(ev[EV_MMA(l)], s0);
        } else {
            k_gemm_mma64_dec<<<N_AST / 64, 256, 104448, s0>>>(Sh, Sl,
                Whg + (size_t)l * 16384, Wlg + (size_t)l * 16384,
                Mta, b_ast + l * HD, dW, db, logits, pred, write_pred);
        }

        const float* ta = ia; ia = oa; oa = (float*)ta;
        if (!last) { const float* tt = it; it = ot; ot = (float*)tt; }
    }
}

// round 15
// speedup vs baseline: 1.1451x; 1.1013x over previous
#include <cuda_runtime.h>
#include <cuda_bf16.h>
#include <cuda_fp16.h>
#include <cstdint>

#define N_AST   200000
#define N_TEST  10000
#define HD      128
#define NLAYERS 5

// ---------------- scratch (device globals; no allocation allowed) ----------
// h_ast buffers are fp16 now (12.8M floats of space each)
#define F_HA   0u
#define F_HB   12800000u
#define F_SH   25600000u      // Sh bf16
#define F_SL   38400000u      // Sl bf16
#define F_MTA  51200000u
#define F_XTA  76800000u
#define F_STB  78080000u
#define F_HTA  79360000u
#define F_HTB  80640000u
#define F_WS   81920000u      // Wh/Wl pre-split (81920 floats)
#define F_WC   82001920u      // Wch/Wcl pre-split (16384 floats)
#define F_TOT  82018304u
__device__ float g_f[F_TOT];

#define I_OFF_AA 0
#define I_OFF_TA 200001
#define I_OFF_AT 400002
#define I_CUR_AA 410003
#define I_CUR_TA 610003
#define I_CUR_AT 810003
#define I_CSR_AA 820013
#define I_CSR_TA 2820013
#define I_CSR_AT 3320013
#define I_PART0  3820013
#define I_POFF0  3820813
#define I_PART1  3821614
#define I_POFF1  3822414
#define I_PART2  3823215
#define I_POFF2  3824015
#define I_TOT    3824816
__device__ int g_i[I_TOT];

static inline int div_up(int a, int b) { return (a + b - 1) / b; }

#define F_ADDIN  1
#define F_BIAS   2
#define F_RELU   4
#define F_ADDRES 8

// ---------------- streams/events (static init; not device-memory allocs) ----
#define NEV 20
struct SxInit {
    cudaStream_t s1, s2;
    cudaEvent_t ev[NEV];
    SxInit() {
        s1 = nullptr; s2 = nullptr;
        cudaStreamCreateWithFlags(&s1, cudaStreamNonBlocking);
        cudaStreamCreateWithFlags(&s2, cudaStreamNonBlocking);
        for (int i = 0; i < NEV; i++) {
            ev[i] = nullptr;
            cudaEventCreateWithFlags(&ev[i], cudaEventDisableTiming);
        }
    }
};
static SxInit g_sx;
#define EV_ROOT  0
#define EV_ENC   1
#define EV_INITT 2
#define EV_MMA(l) (3 + (l))    // 3..6
#define EV_MTA(l) (7 + (l))    // 7..11
#define EV_AT(l)  (12 + (l))   // 12..15

// ---------------- small utility kernels ------------------------------------
__global__ void k_zero_int(int* __restrict__ p, int n) {
    int i = blockIdx.x * blockDim.x + threadIdx.x;
    if (i < n) p[i] = 0;
}
__global__ void k_hist(const int* __restrict__ dst, int* __restrict__ deg, int E) {
    int e = blockIdx.x * blockDim.x + threadIdx.x;
    if (e < E) atomicAdd(&deg[dst[e]], 1);
}

__global__ void k_blocksum(const int* __restrict__ v, int* __restrict__ part, int n) {
    __shared__ int ws[32];
    int t = threadIdx.x;
    int i = blockIdx.x * 1024 + t;
    int x = (i < n) ? v[i] : 0;
    #pragma unroll
    for (int o = 16; o; o >>= 1) x += __shfl_xor_sync(0xffffffffu, x, o);
    if ((t & 31) == 0) ws[t >> 5] = x;
    __syncthreads();
    if (t < 32) {
        int y = ws[t];
        #pragma unroll
        for (int o = 16; o; o >>= 1) y += __shfl_xor_sync(0xffffffffu, y, o);
        if (t == 0) part[blockIdx.x] = y;
    }
}
__global__ void k_exscan(const int* __restrict__ v, int* __restrict__ offs, int n) {
    __shared__ int wsum[32];
    __shared__ int carry;
    int t = threadIdx.x;
    if (t == 0) carry = 0;
    __syncthreads();
    for (int base = 0; base < n; base += 1024) {
        int i = base + t;
        int orig = (i < n) ? v[i] : 0;
        int x = orig;
        #pragma unroll
        for (int o = 1; o < 32; o <<= 1) {
            int y = __shfl_up_sync(0xffffffffu, x, o);
            if ((t & 31) >= o) x += y;
        }
        if ((t & 31) == 31) wsum[t >> 5] = x;
        __syncthreads();
        if (t < 32) {
            int w = wsum[t];
            #pragma unroll
            for (int o = 1; o < 32; o <<= 1) {
                int y = __shfl_up_sync(0xffffffffu, w, o);
                if (t >= o) w += y;
            }
            wsum[t] = w;
        }
        __syncthreads();
        int woff = (t >= 32) ? wsum[(t >> 5) - 1] : 0;
        int incl = x + woff + carry;
        if (i < n) offs[i] = incl - orig;
        __syncthreads();
        if (t == 1023) carry = incl;
        __syncthreads();
    }
    if (t == 0) offs[n] = carry;
}
__global__ void k_scan_apply(const int* __restrict__ v, const int* __restrict__ poffs,
                             int* __restrict__ offs, int* __restrict__ cur, int n) {
    __shared__ int wsum[32];
    int t = threadIdx.x;
    int i = blockIdx.x * 1024 + t;
    int orig = (i < n) ? v[i] : 0;
    int x = orig;
    #pragma unroll
    for (int o = 1; o < 32; o <<= 1) {
        int y = __shfl_up_sync(0xffffffffu, x, o);
        if ((t & 31) >= o) x += y;
    }
    if ((t & 31) == 31) wsum[t >> 5] = x;
    __syncthreads();
    if (t < 32) {
        int w = wsum[t];
        #pragma unroll
        for (int o = 1; o < 32; o <<= 1) {
            int y = __shfl_up_sync(0xffffffffu, w, o);
            if (t >= o) w += y;
        }
        wsum[t] = w;
    }
    __syncthreads();
    int woff = (t >= 32) ? wsum[(t >> 5) - 1] : 0;
    int incl = x + woff + poffs[blockIdx.x];
    if (i < n) {
        int ex = incl - orig;
        offs[i] = ex;
        cur[i] = ex;
    }
    if (i == 0) offs[n] = poffs[gridDim.x];
}

__global__ void k_build(const int* __restrict__ dst, const int* __restrict__ src,
                        int* __restrict__ cursor, int* __restrict__ csr, int E) {
    int e = blockIdx.x * blockDim.x + threadIdx.x;
    if (e < E) {
        int p = atomicAdd(&cursor[dst[e]], 1);
        csr[p] = src[e];
    }
}
__global__ void k_init_test(const float* __restrict__ temb, float* __restrict__ h) {
    int i = blockIdx.x * blockDim.x + threadIdx.x;
    if (i < N_TEST * HD) h[i] = temb[i & 127];
}

__global__ void k_split_w(const float* __restrict__ W,
                          __nv_bfloat16* __restrict__ Wh, __nv_bfloat16* __restrict__ Wl) {
    int i = blockIdx.x * blockDim.x + threadIdx.x;
    if (i >= NLAYERS * 16384) return;
    int l = i >> 14, r = i & 16383;
    int k = r >> 7, n = r & 127;
    float w = W[l * 16384 + k * 128 + n];
    __nv_bfloat16 h = __float2bfloat16_rn(w);
    __nv_bfloat16 lo = __float2bfloat16_rn(w - __bfloat162float(h));
    Wh[l * 16384 + n * 128 + k] = h;
    Wl[l * 16384 + n * 128 + k] = lo;
}

__global__ void k_split_wc(const float* __restrict__ Wc,
                           __nv_bfloat16* __restrict__ Wh, __nv_bfloat16* __restrict__ Wl) {
    int i = blockIdx.x * blockDim.x + threadIdx.x;
    if (i >= 16384) return;
    int k = i >> 6, n = i & 63;
    float w = Wc[i];
    __nv_bfloat16 h = __float2bfloat16_rn(w);
    __nv_bfloat16 lo = __float2bfloat16_rn(w - __bfloat162float(h));
    Wh[n * 256 + k] = h;
    Wl[n * 256 + k] = lo;
}

// ---------------- MMA primitive ----------------------------------------------
#define APAD 136
__device__ __forceinline__ void mma16816(float c[4], const uint32_t a[4],
                                         uint32_t b0, uint32_t b1) {
    asm volatile(
        "mma.sync.aligned.m16n8k16.row.col.f32.bf16.bf16.f32 "
        "{%0,%1,%2,%3},{%4,%5,%6,%7},{%8,%9},{%0,%1,%2,%3};"
        : "+f"(c[0]), "+f"(c[1]), "+f"(c[2]), "+f"(c[3])
        : "r"(a[0]), "r"(a[1]), "r"(a[2]), "r"(a[3]), "r"(b0), "r"(b1));
}
__device__ __forceinline__ void split2(float2 x, uint32_t& hi, uint32_t& lo) {
    __nv_bfloat16 h0 = __float2bfloat16_rn(x.x);
    __nv_bfloat16 h1 = __float2bfloat16_rn(x.y);
    __nv_bfloat16 l0 = __float2bfloat16_rn(x.x - __bfloat162float(h0));
    __nv_bfloat16 l1 = __float2bfloat16_rn(x.y - __bfloat162float(h1));
    __nv_bfloat162 hh = __halves2bfloat162(h0, h1);
    __nv_bfloat162 ll = __halves2bfloat162(l0, l1);
    hi = *(uint32_t*)&hh;
    lo = *(uint32_t*)&ll;
}

// ---------------- tensor-core encoder (fp16 h out) ----------------------------
#define EAPAD 260
#define EWPAD 264
#define SM_ENC_A (64 * EWPAD * 2 * 2)
#define SM_ENC_TOT (SM_ENC_A + 32 * EAPAD * 4)

__global__ void __launch_bounds__(256) k_enc_mma(
    const int* __restrict__ label, const float* __restrict__ content,
    const float* __restrict__ emb,
    const __nv_bfloat16* __restrict__ Wch_g, const __nv_bfloat16* __restrict__ Wcl_g,
    const float* __restrict__ bc, __half* __restrict__ h)
{
    extern __shared__ __align__(16) char smraw[];
    __nv_bfloat16* Wh = (__nv_bfloat16*)smraw;         // [64][EWPAD]
    __nv_bfloat16* Wl = Wh + 64 * EWPAD;
    float* As = (float*)(smraw + SM_ENC_A);            // [32][EAPAD]
    int t = threadIdx.x;
    int m0 = blockIdx.x * 32;

    #pragma unroll
    for (int j = 0; j < 8; j++) {
        int i = t + 256 * j;
        int nrow = i >> 5, kg = i & 31;
        *(uint4*)&Wh[nrow * EWPAD + kg * 8] = ((const uint4*)Wch_g)[i];
        *(uint4*)&Wl[nrow * EWPAD + kg * 8] = ((const uint4*)Wcl_g)[i];
    }
    #pragma unroll
    for (int j = 0; j < 8; j++) {
        int i = t + 256 * j;
        int r = i >> 6, cg = i & 63;
        *(float4*)&As[r * EAPAD + cg * 4] =
            ((const float4*)content)[(size_t)(m0 + r) * 64 + cg];
    }
    __syncthreads();

    int warp = t >> 5, lane = t & 31;
    int wm = warp & 1, wn = warp >> 1;
    int q = lane & 3, rr = lane >> 2;

    float c[2][4];
    #pragma unroll
    for (int j = 0; j < 2; j++)
        c[j][0] = c[j][1] = c[j][2] = c[j][3] = 0.f;

    #pragma unroll 4
    for (int ks = 0; ks < 16; ks++) {
        int kb = ks * 16;
        const float* ap = &As[(wm * 16 + rr) * EAPAD + kb + q * 2];
        float2 x0 = *(const float2*)(ap);
        float2 x1 = *(const float2*)(ap + 8 * EAPAD);
        float2 x2 = *(const float2*)(ap + 8);
        float2 x3 = *(const float2*)(ap + 8 * EAPAD + 8);
        uint32_t ah[4], al[4];
        split2(x0, ah[0], al[0]);
        split2(x1, ah[1], al[1]);
        split2(x2, ah[2], al[2]);
        split2(x3, ah[3], al[3]);
        #pragma unroll
        for (int nt = 0; nt < 2; nt++) {
            const __nv_bfloat16* bph = Wh + (wn * 16 + nt * 8 + rr) * EWPAD + kb + q * 2;
            const __nv_bfloat16* bpl = Wl + (wn * 16 + nt * 8 + rr) * EWPAD + kb + q * 2;
            uint32_t bh0 = *(const uint32_t*)bph;
            uint32_t bh1 = *(const uint32_t*)(bph + 8);
            uint32_t bl0 = *(const uint32_t*)bpl;
            uint32_t bl1 = *(const uint32_t*)(bpl + 8);
            mma16816(c[nt], ah, bh0, bh1);
            mma16816(c[nt], ah, bl0, bl1);
            mma16816(c[nt], al, bh0, bh1);
        }
    }

    #pragma unroll
    for (int nt = 0; nt < 2; nt++) {
        #pragma unroll
        for (int half = 0; half < 2; half++) {
            int row = m0 + wm * 16 + half * 8 + rr;
            int col = wn * 16 + nt * 8 + q * 2;
            float2 bb = *(const float2*)&bc[col];
            *(__half2*)&h[(size_t)row * HD + 64 + col] =
                __floats2half2_rn(c[nt][half * 2] + bb.x, c[nt][half * 2 + 1] + bb.y);
        }
    }
    for (int i = t; i < 32 * 64; i += 256) {
        int r = i >> 6, col = i & 63;
        int gn = m0 + r;
        h[(size_t)gn * HD + col] = __float2half(emb[(size_t)label[gn] * 64 + col]);
    }
}

// ---------------- tensor-core GEMM (fp16 h out / residual) -------------------
__global__ void __launch_bounds__(256) k_gemm_mma64(
    const __nv_bfloat16* __restrict__ Ah_g, const __nv_bfloat16* __restrict__ Al_g,
    const __nv_bfloat16* __restrict__ Wh_g, const __nv_bfloat16* __restrict__ Wl_g,
    const float* __restrict__ AddIn, const float* __restrict__ bias,
    const __half* __restrict__ res, __half* __restrict__ out, int M, int addres)
{
    extern __shared__ __align__(16) char smraw[];
    __nv_bfloat16* Ah = (__nv_bfloat16*)smraw;
    __nv_bfloat16* Al = Ah + 64 * APAD;
    __nv_bfloat16* Wh = Al + 64 * APAD;
    __nv_bfloat16* Wl = Wh + 128 * APAD;
    int t = threadIdx.x;
    int m0 = blockIdx.x * 64;

    #pragma unroll
    for (int j = 0; j < 8; j++) {
        int i = t + 256 * j;
        int nrow = i >> 4, kg = i & 15;
        *(uint4*)&Wh[nrow * APAD + kg * 8] = ((const uint4*)Wh_g)[i];
        *(uint4*)&Wl[nrow * APAD + kg * 8] = ((const uint4*)Wl_g)[i];
    }
    #pragma unroll
    for (int j = 0; j < 4; j++) {
        int i = t + 256 * j;
        int r = i >> 4, kg = i & 15;
        long gr = m0 + r;
        uint4 vh = make_uint4(0u, 0u, 0u, 0u), vl = vh;
        if (gr < M) {
            vh = ((const uint4*)Ah_g)[gr * 16 + kg];
            vl = ((const uint4*)Al_g)[gr * 16 + kg];
        }
        *(uint4*)&Ah[r * APAD + kg * 8] = vh;
        *(uint4*)&Al[r * APAD + kg * 8] = vl;
    }
    __syncthreads();

    int warp = t >> 5, lane = t & 31;
    int wm = warp & 1, wn = warp >> 1;
    int q = lane & 3, rr = lane >> 2;

    float c[2][4][4];
    #pragma unroll
    for (int i = 0; i < 2; i++)
        #pragma unroll
        for (int j = 0; j < 4; j++)
            c[i][j][0] = c[i][j][1] = c[i][j][2] = c[i][j][3] = 0.f;

    #pragma unroll
    for (int term = 0; term < 3; term++) {
        const __nv_bfloat16* Ab = (term == 2) ? Al : Ah;
        const __nv_bfloat16* Bb = (term == 1) ? Wl : Wh;
        #pragma unroll
        for (int ks = 0; ks < 8; ks++) {
            int kb = ks * 16;
            uint32_t a[2][4];
            #pragma unroll
            for (int mt = 0; mt < 2; mt++) {
                const __nv_bfloat16* ap = Ab + (wm * 32 + mt * 16 + rr) * APAD + kb + q * 2;
                a[mt][0] = *(const uint32_t*)(ap);
                a[mt][1] = *(const uint32_t*)(ap + 8 * APAD);
                a[mt][2] = *(const uint32_t*)(ap + 8);
                a[mt][3] = *(const uint32_t*)(ap + 8 * APAD + 8);
            }
            #pragma unroll
            for (int nt = 0; nt < 4; nt++) {
                const __nv_bfloat16* bp = Bb + (wn * 32 + nt * 8 + rr) * APAD + kb + q * 2;
                uint32_t b0 = *(const uint32_t*)bp;
                uint32_t b1 = *(const uint32_t*)(bp + 8);
                mma16816(c[0][nt], a[0], b0, b1);
                mma16816(c[1][nt], a[1], b0, b1);
            }
        }
    }

    #pragma unroll
    for (int mt = 0; mt < 2; mt++) {
        #pragma unroll
        for (int half = 0; half < 2; half++) {
            int row = m0 + wm * 32 + mt * 16 + half * 8 + rr;
            if (row >= M) continue;
            #pragma unroll
            for (int nt = 0; nt < 4; nt++) {
                int col = wn * 32 + nt * 8 + q * 2;
                size_t o = (size_t)row * HD + col;
                float2 v = make_float2(c[mt][nt][half * 2], c[mt][nt][half * 2 + 1]);
                float2 d = *(const float2*)&AddIn[o];
                float2 bb = *(const float2*)&bias[col];
                v.x += d.x + bb.x;
                v.y += d.y + bb.y;
                v.x = fmaxf(v.x, 0.f);
                v.y = fmaxf(v.y, 0.f);
                if (addres) {
                    float2 rv = __half22float2(*(const __half2*)&res[o]);
                    v.x += rv.x; v.y += rv.y;
                }
                *(__half2*)&out[o] = __floats2half2_rn(v.x, v.y);
            }
        }
    }
}

// ---------------- last-layer variant: MMA + fused decode ---------------------
__global__ void __launch_bounds__(256) k_gemm_mma64_dec(
    const __nv_bfloat16* __restrict__ Ah_g, const __nv_bfloat16* __restrict__ Al_g,
    const __nv_bfloat16* __restrict__ Wh_g, const __nv_bfloat16* __restrict__ Wl_g,
    const float* __restrict__ AddIn, const float* __restrict__ bias,
    const float* __restrict__ dW, const float* __restrict__ db,
    float* __restrict__ logits, float* __restrict__ pred, int write_pred)
{
    extern __shared__ __align__(16) char smraw[];
    __nv_bfloat16* Ah = (__nv_bfloat16*)smraw;
    __nv_bfloat16* Al = Ah + 64 * APAD;
    __nv_bfloat16* Wh = Al + 64 * APAD;
    __nv_bfloat16* Wl = Wh + 128 * APAD;
    int t = threadIdx.x;
    int m0 = blockIdx.x * 64;

    #pragma unroll
    for (int j = 0; j < 8; j++) {
        int i = t + 256 * j;
        int nrow = i >> 4, kg = i & 15;
        *(uint4*)&Wh[nrow * APAD + kg * 8] = ((const uint4*)Wh_g)[i];
        *(uint4*)&Wl[nrow * APAD + kg * 8] = ((const uint4*)Wl_g)[i];
    }
    #pragma unroll
    for (int j = 0; j < 4; j++) {
        int i = t + 256 * j;
        int r = i >> 4, kg = i & 15;
        long gr = m0 + r;
        *(uint4*)&Ah[r * APAD + kg * 8] = ((const uint4*)Ah_g)[gr * 16 + kg];
        *(uint4*)&Al[r * APAD + kg * 8] = ((const uint4*)Al_g)[gr * 16 + kg];
    }
    __syncthreads();

    int warp = t >> 5, lane = t & 31;
    int wm = warp & 1, wn = warp >> 1;
    int q = lane & 3, rr = lane >> 2;

    float c[2][4][4];
    #pragma unroll
    for (int i = 0; i < 2; i++)
        #pragma unroll
        for (int j = 0; j < 4; j++)
            c[i][j][0] = c[i][j][1] = c[i][j][2] = c[i][j][3] = 0.f;

    #pragma unroll
    for (int term = 0; term < 3; term++) {
        const __nv_bfloat16* Ab = (term == 2) ? Al : Ah;
        const __nv_bfloat16* Bb = (term == 1) ? Wl : Wh;
        #pragma unroll
        for (int ks = 0; ks < 8; ks++) {
            int kb = ks * 16;
            uint32_t a[2][4];
            #pragma unroll
            for (int mt = 0; mt < 2; mt++) {
                const __nv_bfloat16* ap = Ab + (wm * 32 + mt * 16 + rr) * APAD + kb + q * 2;
                a[mt][0] = *(const uint32_t*)(ap);
                a[mt][1] = *(const uint32_t*)(ap + 8 * APAD);
                a[mt][2] = *(const uint32_t*)(ap + 8);
                a[mt][3] = *(const uint32_t*)(ap + 8 * APAD + 8);
            }
            #pragma unroll
            for (int nt = 0; nt < 4; nt++) {
                const __nv_bfloat16* bp = Bb + (wn * 32 + nt * 8 + rr) * APAD + kb + q * 2;
                uint32_t b0 = *(const uint32_t*)bp;
                uint32_t b1 = *(const uint32_t*)(bp + 8);
                mma16816(c[0][nt], a[0], b0, b1);
                mma16816(c[1][nt], a[1], b0, b1);
            }
        }
    }

    float l0[4] = {0.f, 0.f, 0.f, 0.f};
    float l1[4] = {0.f, 0.f, 0.f, 0.f};
    #pragma unroll
    for (int mt = 0; mt < 2; mt++) {
        #pragma unroll
        for (int half = 0; half < 2; half++) {
            int row = m0 + wm * 32 + mt * 16 + half * 8 + rr;
            int ridx = mt * 2 + half;
            #pragma unroll
            for (int nt = 0; nt < 4; nt++) {
                int col = wn * 32 + nt * 8 + q * 2;
                size_t o = (size_t)row * HD + col;
                float2 v = make_float2(c[mt][nt][half * 2], c[mt][nt][half * 2 + 1]);
                float2 d = *(const float2*)&AddIn[o];
                float2 bb = *(const float2*)&bias[col];
                v.x = fmaxf(v.x + d.x + bb.x, 0.f);
                v.y = fmaxf(v.y + d.y + bb.y, 0.f);
                float2 w0 = *(const float2*)&dW[col * 2];
                float2 w1 = *(const float2*)&dW[(col + 1) * 2];
                l0[ridx] += v.x * w0.x + v.y * w1.x;
                l1[ridx] += v.x * w0.y + v.y * w1.y;
            }
        }
    }
    #pragma unroll
    for (int ridx = 0; ridx < 4; ridx++) {
        l0[ridx] += __shfl_xor_sync(0xffffffffu, l0[ridx], 1);
        l0[ridx] += __shfl_xor_sync(0xffffffffu, l0[ridx], 2);
        l1[ridx] += __shfl_xor_sync(0xffffffffu, l1[ridx], 1);
        l1[ridx] += __shfl_xor_sync(0xffffffffu, l1[ridx], 2);
    }
    __syncthreads();
    float* dsm = (float*)smraw;
    if (q == 0) {
        #pragma unroll
        for (int mt = 0; mt < 2; mt++) {
            #pragma unroll
            for (int half = 0; half < 2; half++) {
                int rloc = wm * 32 + mt * 16 + half * 8 + rr;
                int ridx = mt * 2 + half;
                dsm[rloc * 8 + wn * 2 + 0] = l0[ridx];
                dsm[rloc * 8 + wn * 2 + 1] = l1[ridx];
            }
        }
    }
    __syncthreads();
    if (t < 64) {
        float L0 = dsm[t * 8] + dsm[t * 8 + 2] + dsm[t * 8 + 4] + dsm[t * 8 + 6] + db[0];
        float L1 = dsm[t * 8 + 1] + dsm[t * 8 + 3] + dsm[t * 8 + 5] + dsm[t * 8 + 7] + db[1];
        long grow = m0 + t;
        logits[grow * 2]     = L0;
        logits[grow * 2 + 1] = L1;
        if (write_pred) {
            float mx = fmaxf(L0, L1);
            float e0 = expf(L0 - mx), e1 = expf(L1 - mx);
            float s = e0 + e1;
            pred[grow * 2]     = e0 / s;
            pred[grow * 2 + 1] = e1 / s;
        }
    }
}

// ---------------- FFMA GEMM with fused epilogue (small M, fp32 test path) ----
__global__ void __launch_bounds__(256) k_gemm_ep(
    const float* __restrict__ A, const float* __restrict__ W,
    const float* __restrict__ AddIn, const float* __restrict__ bias,
    const float* __restrict__ res, float* __restrict__ out, int M, int flags)
{
    extern __shared__ float sm[];
    float* Ws = sm;
    float* As = sm + 16384;
    int t = threadIdx.x;
    const float4* W4 = (const float4*)W;
    float4* Ws4 = (float4*)Ws;
    #pragma unroll
    for (int i = 0; i < 16; i++) Ws4[t + 256 * i] = W4[t + 256 * i];
    int m0 = blockIdx.x * 64;
    #pragma unroll
    for (int i = 0; i < 8; i++) {
        int idx = t + 256 * i;
        int r = idx >> 5, cc = idx & 31;
        int gr = m0 + r;
        float4 v = (gr < M) ? ((const float4*)A)[(size_t)gr * 32 + cc]
                            : make_float4(0.f, 0.f, 0.f, 0.f);
        *(float4*)&As[r * 132 + cc * 4] = v;
    }
    __syncthreads();
    int c0 = (t & 31) * 4;
    int r0 = (t >> 5) * 8;
    float acc[8][4];
    #pragma unroll
    for (int i = 0; i < 8; i++) { acc[i][0] = acc[i][1] = acc[i][2] = acc[i][3] = 0.f; }
    #pragma unroll 2
    for (int k = 0; k < 128; k++) {
        float4 w = *(const float4*)&Ws[k * 128 + c0];
        #pragma unroll
        for (int i = 0; i < 8; i++) {
            float a = As[(r0 + i) * 132 + k];
            acc[i][0] += a * w.x;
            acc[i][1] += a * w.y;
            acc[i][2] += a * w.z;
            acc[i][3] += a * w.w;
        }
    }
    float4 bb = make_float4(0.f, 0.f, 0.f, 0.f);
    if (flags & F_BIAS) bb = *(const float4*)&bias[c0];
    #pragma unroll
    for (int i = 0; i < 8; i++) {
        int gr = m0 + r0 + i;
        if (gr < M) {
            size_t o = (size_t)gr * HD + c0;
            float4 v = make_float4(acc[i][0] + bb.x, acc[i][1] + bb.y,
                                   acc[i][2] + bb.z, acc[i][3] + bb.w);
            if (flags & F_ADDIN) {
                float4 d = *(const float4*)&AddIn[o];
                v.x += d.x; v.y += d.y; v.z += d.z; v.w += d.w;
            }
            if (flags & F_RELU) {
                v.x = fmaxf(v.x, 0.f); v.y = fmaxf(v.y, 0.f);
                v.z = fmaxf(v.z, 0.f); v.w = fmaxf(v.w, 0.f);
            }
            if (flags & F_ADDRES) {
                float4 rv = *(const float4*)&res[o];
                v.x += rv.x; v.y += rv.y; v.z += rv.z; v.w += rv.w;
            }
            *(float4*)&out[o] = v;
        }
    }
}

// ---------------- mean aggregation (fp32 rows in, fp32 out: Mta) -------------
__global__ void k_agg(const float* __restrict__ X,
                      const int* __restrict__ offs, const int* __restrict__ csr,
                      float* __restrict__ out, int n)
{
    int node = (blockIdx.x * blockDim.x + threadIdx.x) >> 5;
    if (node >= n) return;
    int lane = threadIdx.x & 31;
    int s0 = offs[node], s1 = offs[node + 1];
    float4 a = make_float4(0.f, 0.f, 0.f, 0.f);
    for (int e0 = s0; e0 < s1; e0 += 32) {
        int idx = (e0 + lane < s1) ? csr[e0 + lane] : 0;
        int m = min(32, s1 - e0);
        #pragma unroll 8
        for (int j = 0; j < m; j++) {
            int s = __shfl_sync(0xffffffffu, idx, j);
            float4 v = *(const float4*)&X[(size_t)s * HD + lane * 4];
            a.x += v.x; a.y += v.y; a.z += v.z; a.w += v.w;
        }
    }
    float inv = 1.f / (float)((s1 - s0) > 0 ? (s1 - s0) : 1);
    *(float4*)&out[(size_t)node * HD + lane * 4] =
        make_float4(a.x * inv, a.y * inv, a.z * inv, a.w * inv);
}

// ---------------- mean aggregation (fp16 rows in, fp32 out: St) --------------
__global__ void k_agg_h(const __half* __restrict__ X,
                        const int* __restrict__ offs, const int* __restrict__ csr,
                        float* __restrict__ out, int n)
{
    int node = (blockIdx.x * blockDim.x + threadIdx.x) >> 5;
    if (node >= n) return;
    int lane = threadIdx.x & 31;
    int s0 = offs[node], s1 = offs[node + 1];
    float4 a = make_float4(0.f, 0.f, 0.f, 0.f);
    for (int e0 = s0; e0 < s1; e0 += 32) {
        int idx = (e0 + lane < s1) ? csr[e0 + lane] : 0;
        int m = min(32, s1 - e0);
        #pragma unroll 8
        for (int j = 0; j < m; j++) {
            int s = __shfl_sync(0xffffffffu, idx, j);
            uint2 raw = *(const uint2*)&X[(size_t)s * HD + lane * 4];
            float2 f01 = __half22float2(*(__half2*)&raw.x);
            float2 f23 = __half22float2(*(__half2*)&raw.y);
            a.x += f01.x; a.y += f01.y; a.z += f23.x; a.w += f23.y;
        }
    }
    float inv = 1.f / (float)((s1 - s0) > 0 ? (s1 - s0) : 1);
    *(float4*)&out[(size_t)node * HD + lane * 4] =
        make_float4(a.x * inv, a.y * inv, a.z * inv, a.w * inv);
}

// ---------------- mean aggregation (fp16 rows in, bf16 hi/lo split out) ------
__global__ void k_agg_bf_h(const __half* __restrict__ X,
                           const int* __restrict__ offs, const int* __restrict__ csr,
                           __nv_bfloat16* __restrict__ Sh, __nv_bfloat16* __restrict__ Sl,
                           int n)
{
    int node = (blockIdx.x * blockDim.x + threadIdx.x) >> 5;
    if (node >= n) return;
    int lane = threadIdx.x & 31;
    int s0 = offs[node], s1 = offs[node + 1];
    float4 a = make_float4(0.f, 0.f, 0.f, 0.f);
    for (int e0 = s0; e0 < s1; e0 += 32) {
        int idx = (e0 + lane < s1) ? csr[e0 + lane] : 0;
        int m = min(32, s1 - e0);
        #pragma unroll 8
        for (int j = 0; j < m; j++) {
            int s = __shfl_sync(0xffffffffu, idx, j);
            uint2 raw = *(const uint2*)&X[(size_t)s * HD + lane * 4];
            float2 f01 = __half22float2(*(__half2*)&raw.x);
            float2 f23 = __half22float2(*(__half2*)&raw.y);
            a.x += f01.x; a.y += f01.y; a.z += f23.x; a.w += f23.y;
        }
    }
    float inv = 1.f / (float)((s1 - s0) > 0 ? (s1 - s0) : 1);
    const float mv[4] = {a.x * inv, a.y * inv, a.z * inv, a.w * inv};
    __nv_bfloat16 hh[4], ll[4];
    #pragma unroll
    for (int u = 0; u < 4; u++) {
        hh[u] = __float2bfloat16_rn(mv[u]);
        ll[u] = __float2bfloat16_rn(mv[u] - __bfloat162float(hh[u]));
    }
    size_t o = (size_t)node * HD + lane * 4;
    *(uint2*)&Sh[o] = *(uint2*)hh;
    *(uint2*)&Sl[o] = *(uint2*)ll;
}

// ---------------- launch ----------------------------------------------------
extern "C" void kernel_launch(void* const* d_in, const int* in_sizes, int n_in,
                              void* d_out, int out_size)
{
    const int*   ast_label   = (const int*)d_in[0];
    const float* ast_content = (const float*)d_in[1];
    const int* src_aa = (const int*)d_in[2];
    const int* dst_aa = (const int*)d_in[3];
    const int* src_at = (const int*)d_in[4];
    const int* dst_at = (const int*)d_in[5];
    const int* src_ta = (const int*)d_in[6];
    const int* dst_ta = (const int*)d_in[7];
    int E_aa = in_sizes[2], E_at = in_sizes[4], E_ta = in_sizes[6];

    int p = 8;
    if (n_in > 8 && in_sizes[8] == 1) p = 9;
    const float* emb    = (const float*)d_in[p + 0];
    const float* Wc     = (const float*)d_in[p + 1];
    const float* bc     = (const float*)d_in[p + 2];
    const float* temb   = (const float*)d_in[p + 3];
    const float* W_aa   = (const float*)d_in[p + 4];
    const float* W_at   = (const float*)d_in[p + 5];
    const float* W_ta   = (const float*)d_in[p + 6];
    const float* b_ast  = (const float*)d_in[p + 7];
    const float* b_test = (const float*)d_in[p + 8];
    const float* dW     = (const float*)d_in[p + 9];
    const float* db     = (const float*)d_in[p + 10];

    float* F = nullptr;
    int*   I = nullptr;
    cudaGetSymbolAddress((void**)&F, g_f);
    cudaGetSymbolAddress((void**)&I, g_i);

    cudaFuncSetAttribute(k_gemm_ep,        cudaFuncAttributeMaxDynamicSharedMemorySize, 99328);
    cudaFuncSetAttribute(k_gemm_mma64,     cudaFuncAttributeMaxDynamicSharedMemorySize, 104448);
    cudaFuncSetAttribute(k_gemm_mma64_dec, cudaFuncAttributeMaxDynamicSharedMemorySize, 104448);
    cudaFuncSetAttribute(k_enc_mma,        cudaFuncAttributeMaxDynamicSharedMemorySize, SM_ENC_TOT);

    __half* hA = (__half*)(F + F_HA);
    __half* hB = (__half*)(F + F_HB);
    __nv_bfloat16* Sh = (__nv_bfloat16*)(F + F_SH);
    __nv_bfloat16* Sl = (__nv_bfloat16*)(F + F_SL);
    float* Mta = F + F_MTA;
    float* Xta = F + F_XTA;  float* St  = F + F_STB;
    float* hTA = F + F_HTA;  float* hTB = F + F_HTB;
    __nv_bfloat16* Whg  = (__nv_bfloat16*)(F + F_WS);
    __nv_bfloat16* Wlg  = (__nv_bfloat16*)(F + F_WS + 40960u);
    __nv_bfloat16* Wchg = (__nv_bfloat16*)(F + F_WC);
    __nv_bfloat16* Wclg = (__nv_bfloat16*)(F + F_WC + 8192u);

    int* off_aa = I + I_OFF_AA; int* off_ta = I + I_OFF_TA; int* off_at = I + I_OFF_AT;
    int* cur_aa = I + I_CUR_AA; int* cur_ta = I + I_CUR_TA; int* cur_at = I + I_CUR_AT;
    int* csr_aa = I + I_CSR_AA; int* csr_ta = I + I_CSR_TA; int* csr_at = I + I_CSR_AT;
    int* part0 = I + I_PART0; int* poff0 = I + I_POFF0;
    int* part1 = I + I_PART1; int* poff1 = I + I_POFF1;
    int* part2 = I + I_PART2; int* poff2 = I + I_POFF2;

    int nb_ast  = div_up(N_AST, 1024);
    int nb_test = div_up(N_TEST, 1024);

    cudaStream_t s0 = 0, s1 = g_sx.s1, s2 = g_sx.s2;
    cudaEvent_t* ev = g_sx.ev;

    cudaEventRecord(ev[EV_ROOT], s0);
    cudaStreamWaitEvent(s1, ev[EV_ROOT], 0);
    cudaStreamWaitEvent(s2, ev[EV_ROOT], 0);

    // --- s0: aa CSR + split_wc + encode + split_w ---
    k_zero_int<<<div_up(N_AST, 256), 256, 0, s0>>>(cur_aa, N_AST);
    k_hist<<<div_up(E_aa, 256), 256, 0, s0>>>(dst_aa, cur_aa, E_aa);
    k_blocksum<<<nb_ast, 1024, 0, s0>>>(cur_aa, part0, N_AST);
    k_exscan<<<1, 1024, 0, s0>>>(part0, poff0, nb_ast);
    k_scan_apply<<<nb_ast, 1024, 0, s0>>>(cur_aa, poff0, off_aa, cur_aa, N_AST);
    k_build<<<div_up(E_aa, 256), 256, 0, s0>>>(dst_aa, src_aa, cur_aa, csr_aa, E_aa);
    k_split_wc<<<div_up(16384, 256), 256, 0, s0>>>(Wc, Wchg, Wclg);
    k_enc_mma<<<N_AST / 32, 256, SM_ENC_TOT, s0>>>(ast_label, ast_content, emb,
                                                   Wchg, Wclg, bc, hA);
    cudaEventRecord(ev[EV_ENC], s0);
    k_split_w<<<div_up(NLAYERS * 16384, 256), 256, 0, s0>>>(W_aa, Whg, Wlg);

    // --- s1: ta CSR + init_test ---
    k_zero_int<<<div_up(N_AST, 256), 256, 0, s1>>>(cur_ta, N_AST);
    k_hist<<<div_up(E_ta, 256), 256, 0, s1>>>(dst_ta, cur_ta, E_ta);
    k_blocksum<<<nb_ast, 1024, 0, s1>>>(cur_ta, part1, N_AST);
    k_exscan<<<1, 1024, 0, s1>>>(part1, poff1, nb_ast);
    k_scan_apply<<<nb_ast, 1024, 0, s1>>>(cur_ta, poff1, off_ta, cur_ta, N_AST);
    k_build<<<div_up(E_ta, 256), 256, 0, s1>>>(dst_ta, src_ta, cur_ta, csr_ta, E_ta);
    k_init_test<<<div_up(N_TEST * HD, 256), 256, 0, s1>>>(temb, hTA);
    cudaEventRecord(ev[EV_INITT], s1);

    // --- s2: at CSR ---
    k_zero_int<<<div_up(N_TEST, 256), 256, 0, s2>>>(cur_at, N_TEST);
    k_hist<<<div_up(E_at, 256), 256, 0, s2>>>(dst_at, cur_at, E_at);
    k_blocksum<<<nb_test, 1024, 0, s2>>>(cur_at, part2, N_TEST);
    k_exscan<<<1, 1024, 0, s2>>>(part2, poff2, nb_test);
    k_scan_apply<<<nb_test, 1024, 0, s2>>>(cur_at, poff2, off_at, cur_at, N_TEST);
    k_build<<<div_up(E_at, 256), 256, 0, s2>>>(dst_at, src_at, cur_at, csr_at, E_at);
    cudaStreamWaitEvent(s2, ev[EV_ENC], 0);
    cudaStreamWaitEvent(s2, ev[EV_INITT], 0);

    float* logits = (float*)d_out;
    int write_pred = (out_size >= 4 * N_AST);
    float* pred = logits + 2 * N_AST;

    // --- 5 GCN layers, 3-stream pipeline ---
    const __half* ia = hA; const float* it = hTA;
    __half* oa = hB; float* ot = hTB;
    for (int l = 0; l < NLAYERS; l++) {
        int add  = (l == 1 || l == 3);
        int last = (l == NLAYERS - 1);

        // s2: test-node path (aggSt -> gemmAt)   [dead at last layer]
        if (!last) {
            if (l > 0) cudaStreamWaitEvent(s2, ev[EV_MMA(l - 1)], 0);
            k_agg_h<<<div_up(N_TEST * 32, 256), 256, 0, s2>>>(ia, off_at, csr_at, St, N_TEST);
            k_gemm_ep<<<div_up(N_TEST, 64), 256, 99328, s2>>>(St, W_at + (size_t)l * HD * HD,
                nullptr, b_test + l * HD, it, ot, N_TEST,
                F_BIAS | F_RELU | (add ? F_ADDRES : 0));
            cudaEventRecord(ev[EV_AT(l)], s2);
        }

        // s1: Mta chain (gemmXta -> aggMta)
        if (l > 0) cudaStreamWaitEvent(s1, ev[EV_AT(l - 1)], 0);
        k_gemm_ep<<<div_up(N_TEST, 64), 256, 99328, s1>>>(it, W_ta + (size_t)l * HD * HD,
            nullptr, nullptr, nullptr, Xta, N_TEST, 0);
        if (l > 0) cudaStreamWaitEvent(s1, ev[EV_MMA(l - 1)], 0);
        k_agg<<<div_up(N_AST * 32, 256), 256, 0, s1>>>(Xta, off_ta, csr_ta, Mta, N_AST);
        cudaEventRecord(ev[EV_MTA(l)], s1);

        // s0: big gather + tensor-core GEMM
        k_agg_bf_h<<<div_up(N_AST * 32, 256), 256, 0, s0>>>(ia, off_aa, csr_aa, Sh, Sl, N_AST);
        cudaStreamWaitEvent(s0, ev[EV_MTA(l)], 0);
        if (!last) {
            k_gemm_mma64<<<div_up(N_AST, 64), 256, 104448, s0>>>(Sh, Sl,
                Whg + (size_t)l * 16384, Wlg + (size_t)l * 16384,
                Mta, b_ast + l * HD, ia, oa, N_AST, add);
            cudaEventRecord(ev[EV_MMA(l)], s0);
        } else {
            k_gemm_mma64_dec<<<N_AST / 64, 256, 104448, s0>>>(Sh, Sl,
                Whg + (size_t)l * 16384, Wlg + (size_t)l * 16384,
                Mta, b_ast + l * HD, dW, db, logits, pred, write_pred);
        }

        const __half* ta = ia; ia = oa; oa = (__half*)ta;
        if (!last) { const float* tt = it; it = ot; ot = (float*)tt; }
    }
}

// round 16
// speedup vs baseline: 1.2081x; 1.0550x over previous
#include <cuda_runtime.h>
#include <cuda_bf16.h>
#include <cuda_fp16.h>
#include <cstdint>

#define N_AST   200000
#define N_TEST  10000
#define HD      128
#define NLAYERS 5

// ---------------- scratch (device globals; no allocation allowed) ----------
// h buffers fp16; S fp16 (split in-kernel); Mta fp16
#define F_HA   0u
#define F_HB   12800000u
#define F_S    25600000u
#define F_MTA  38400000u
#define F_XTA  51200000u
#define F_STB  52480000u
#define F_HTA  53760000u
#define F_HTB  55040000u
#define F_WS   56320000u      // Wh/Wl pre-split (81920 floats)
#define F_WC   56401920u      // Wch/Wcl pre-split (16384 floats)
#define F_TOT  56418304u
__device__ float g_f[F_TOT];

#define I_OFF_AA 0
#define I_OFF_TA 200001
#define I_OFF_AT 400002
#define I_CUR_AA 410003
#define I_CUR_TA 610003
#define I_CUR_AT 810003
#define I_CSR_AA 820013
#define I_CSR_TA 2820013
#define I_CSR_AT 3320013
#define I_PART0  3820013
#define I_POFF0  3820813
#define I_PART1  3821614
#define I_POFF1  3822414
#define I_PART2  3823215
#define I_POFF2  3824015
#define I_TOT    3824816
__device__ int g_i[I_TOT];

static inline int div_up(int a, int b) { return (a + b - 1) / b; }

#define F_ADDIN  1
#define F_BIAS   2
#define F_RELU   4
#define F_ADDRES 8

// ---------------- streams/events (static init; not device-memory allocs) ----
#define NEV 20
struct SxInit {
    cudaStream_t s1, s2;
    cudaEvent_t ev[NEV];
    SxInit() {
        s1 = nullptr; s2 = nullptr;
        cudaStreamCreateWithFlags(&s1, cudaStreamNonBlocking);
        cudaStreamCreateWithFlags(&s2, cudaStreamNonBlocking);
        for (int i = 0; i < NEV; i++) {
            ev[i] = nullptr;
            cudaEventCreateWithFlags(&ev[i], cudaEventDisableTiming);
        }
    }
};
static SxInit g_sx;
#define EV_ROOT  0
#define EV_ENC   1
#define EV_INITT 2
#define EV_MMA(l) (3 + (l))    // 3..6
#define EV_MTA(l) (7 + (l))    // 7..11
#define EV_AT(l)  (12 + (l))   // 12..15

// ---------------- small utility kernels ------------------------------------
__global__ void k_zero_int(int* __restrict__ p, int n) {
    int i = blockIdx.x * blockDim.x + threadIdx.x;
    if (i < n) p[i] = 0;
}
__global__ void k_hist(const int* __restrict__ dst, int* __restrict__ deg, int E) {
    int e = blockIdx.x * blockDim.x + threadIdx.x;
    if (e < E) atomicAdd(&deg[dst[e]], 1);
}

__global__ void k_blocksum(const int* __restrict__ v, int* __restrict__ part, int n) {
    __shared__ int ws[32];
    int t = threadIdx.x;
    int i = blockIdx.x * 1024 + t;
    int x = (i < n) ? v[i] : 0;
    #pragma unroll
    for (int o = 16; o; o >>= 1) x += __shfl_xor_sync(0xffffffffu, x, o);
    if ((t & 31) == 0) ws[t >> 5] = x;
    __syncthreads();
    if (t < 32) {
        int y = ws[t];
        #pragma unroll
        for (int o = 16; o; o >>= 1) y += __shfl_xor_sync(0xffffffffu, y, o);
        if (t == 0) part[blockIdx.x] = y;
    }
}
__global__ void k_exscan(const int* __restrict__ v, int* __restrict__ offs, int n) {
    __shared__ int wsum[32];
    __shared__ int carry;
    int t = threadIdx.x;
    if (t == 0) carry = 0;
    __syncthreads();
    for (int base = 0; base < n; base += 1024) {
        int i = base + t;
        int orig = (i < n) ? v[i] : 0;
        int x = orig;
        #pragma unroll
        for (int o = 1; o < 32; o <<= 1) {
            int y = __shfl_up_sync(0xffffffffu, x, o);
            if ((t & 31) >= o) x += y;
        }
        if ((t & 31) == 31) wsum[t >> 5] = x;
        __syncthreads();
        if (t < 32) {
            int w = wsum[t];
            #pragma unroll
            for (int o = 1; o < 32; o <<= 1) {
                int y = __shfl_up_sync(0xffffffffu, w, o);
                if (t >= o) w += y;
            }
            wsum[t] = w;
        }
        __syncthreads();
        int woff = (t >= 32) ? wsum[(t >> 5) - 1] : 0;
        int incl = x + woff + carry;
        if (i < n) offs[i] = incl - orig;
        __syncthreads();
        if (t == 1023) carry = incl;
        __syncthreads();
    }
    if (t == 0) offs[n] = carry;
}
__global__ void k_scan_apply(const int* __restrict__ v, const int* __restrict__ poffs,
                             int* __restrict__ offs, int* __restrict__ cur, int n) {
    __shared__ int wsum[32];
    int t = threadIdx.x;
    int i = blockIdx.x * 1024 + t;
    int orig = (i < n) ? v[i] : 0;
    int x = orig;
    #pragma unroll
    for (int o = 1; o < 32; o <<= 1) {
        int y = __shfl_up_sync(0xffffffffu, x, o);
        if ((t & 31) >= o) x += y;
    }
    if ((t & 31) == 31) wsum[t >> 5] = x;
    __syncthreads();
    if (t < 32) {
        int w = wsum[t];
        #pragma unroll
        for (int o = 1; o < 32; o <<= 1) {
            int y = __shfl_up_sync(0xffffffffu, w, o);
            if (t >= o) w += y;
        }
        wsum[t] = w;
    }
    __syncthreads();
    int woff = (t >= 32) ? wsum[(t >> 5) - 1] : 0;
    int incl = x + woff + poffs[blockIdx.x];
    if (i < n) {
        int ex = incl - orig;
        offs[i] = ex;
        cur[i] = ex;
    }
    if (i == 0) offs[n] = poffs[gridDim.x];
}

__global__ void k_build(const int* __restrict__ dst, const int* __restrict__ src,
                        int* __restrict__ cursor, int* __restrict__ csr, int E) {
    int e = blockIdx.x * blockDim.x + threadIdx.x;
    if (e < E) {
        int p = atomicAdd(&cursor[dst[e]], 1);
        csr[p] = src[e];
    }
}
__global__ void k_init_test(const float* __restrict__ temb, float* __restrict__ h) {
    int i = blockIdx.x * blockDim.x + threadIdx.x;
    if (i < N_TEST * HD) h[i] = temb[i & 127];
}

__global__ void k_split_w(const float* __restrict__ W,
                          __nv_bfloat16* __restrict__ Wh, __nv_bfloat16* __restrict__ Wl) {
    int i = blockIdx.x * blockDim.x + threadIdx.x;
    if (i >= NLAYERS * 16384) return;
    int l = i >> 14, r = i & 16383;
    int k = r >> 7, n = r & 127;
    float w = W[l * 16384 + k * 128 + n];
    __nv_bfloat16 h = __float2bfloat16_rn(w);
    __nv_bfloat16 lo = __float2bfloat16_rn(w - __bfloat162float(h));
    Wh[l * 16384 + n * 128 + k] = h;
    Wl[l * 16384 + n * 128 + k] = lo;
}

__global__ void k_split_wc(const float* __restrict__ Wc,
                           __nv_bfloat16* __restrict__ Wh, __nv_bfloat16* __restrict__ Wl) {
    int i = blockIdx.x * blockDim.x + threadIdx.x;
    if (i >= 16384) return;
    int k = i >> 6, n = i & 63;
    float w = Wc[i];
    __nv_bfloat16 h = __float2bfloat16_rn(w);
    __nv_bfloat16 lo = __float2bfloat16_rn(w - __bfloat162float(h));
    Wh[n * 256 + k] = h;
    Wl[n * 256 + k] = lo;
}

// ---------------- MMA primitive ----------------------------------------------
#define APAD 136
__device__ __forceinline__ void mma16816(float c[4], const uint32_t a[4],
                                         uint32_t b0, uint32_t b1) {
    asm volatile(
        "mma.sync.aligned.m16n8k16.row.col.f32.bf16.bf16.f32 "
        "{%0,%1,%2,%3},{%4,%5,%6,%7},{%8,%9},{%0,%1,%2,%3};"
        : "+f"(c[0]), "+f"(c[1]), "+f"(c[2]), "+f"(c[3])
        : "r"(a[0]), "r"(a[1]), "r"(a[2]), "r"(a[3]), "r"(b0), "r"(b1));
}
__device__ __forceinline__ void split2(float2 x, uint32_t& hi, uint32_t& lo) {
    __nv_bfloat16 h0 = __float2bfloat16_rn(x.x);
    __nv_bfloat16 h1 = __float2bfloat16_rn(x.y);
    __nv_bfloat16 l0 = __float2bfloat16_rn(x.x - __bfloat162float(h0));
    __nv_bfloat16 l1 = __float2bfloat16_rn(x.y - __bfloat162float(h1));
    __nv_bfloat162 hh = __halves2bfloat162(h0, h1);
    __nv_bfloat162 ll = __halves2bfloat162(l0, l1);
    hi = *(uint32_t*)&hh;
    lo = *(uint32_t*)&ll;
}
// split a uint4 of 8 halves into 8 bf16 hi + 8 bf16 lo (exact: fp16 in bf16hi+lo)
__device__ __forceinline__ void split_h8(uint4 v, uint4& hi, uint4& lo) {
    const __half2* hp = (const __half2*)&v;
    uint32_t* ho = (uint32_t*)&hi;
    uint32_t* lg = (uint32_t*)&lo;
    #pragma unroll
    for (int u = 0; u < 4; u++) {
        float2 f = __half22float2(hp[u]);
        split2(f, ho[u], lg[u]);
    }
}

// ---------------- tensor-core encoder (fp16 h out) ----------------------------
#define EAPAD 260
#define EWPAD 264
#define SM_ENC_A (64 * EWPAD * 2 * 2)
#define SM_ENC_TOT (SM_ENC_A + 32 * EAPAD * 4)

__global__ void __launch_bounds__(256) k_enc_mma(
    const int* __restrict__ label, const float* __restrict__ content,
    const float* __restrict__ emb,
    const __nv_bfloat16* __restrict__ Wch_g, const __nv_bfloat16* __restrict__ Wcl_g,
    const float* __restrict__ bc, __half* __restrict__ h)
{
    extern __shared__ __align__(16) char smraw[];
    __nv_bfloat16* Wh = (__nv_bfloat16*)smraw;         // [64][EWPAD]
    __nv_bfloat16* Wl = Wh + 64 * EWPAD;
    float* As = (float*)(smraw + SM_ENC_A);            // [32][EAPAD]
    int t = threadIdx.x;
    int m0 = blockIdx.x * 32;

    #pragma unroll
    for (int j = 0; j < 8; j++) {
        int i = t + 256 * j;
        int nrow = i >> 5, kg = i & 31;
        *(uint4*)&Wh[nrow * EWPAD + kg * 8] = ((const uint4*)Wch_g)[i];
        *(uint4*)&Wl[nrow * EWPAD + kg * 8] = ((const uint4*)Wcl_g)[i];
    }
    #pragma unroll
    for (int j = 0; j < 8; j++) {
        int i = t + 256 * j;
        int r = i >> 6, cg = i & 63;
        *(float4*)&As[r * EAPAD + cg * 4] =
            ((const float4*)content)[(size_t)(m0 + r) * 64 + cg];
    }
    __syncthreads();

    int warp = t >> 5, lane = t & 31;
    int wm = warp & 1, wn = warp >> 1;
    int q = lane & 3, rr = lane >> 2;

    float c[2][4];
    #pragma unroll
    for (int j = 0; j < 2; j++)
        c[j][0] = c[j][1] = c[j][2] = c[j][3] = 0.f;

    #pragma unroll 4
    for (int ks = 0; ks < 16; ks++) {
        int kb = ks * 16;
        const float* ap = &As[(wm * 16 + rr) * EAPAD + kb + q * 2];
        float2 x0 = *(const float2*)(ap);
        float2 x1 = *(const float2*)(ap + 8 * EAPAD);
        float2 x2 = *(const float2*)(ap + 8);
        float2 x3 = *(const float2*)(ap + 8 * EAPAD + 8);
        uint32_t ah[4], al[4];
        split2(x0, ah[0], al[0]);
        split2(x1, ah[1], al[1]);
        split2(x2, ah[2], al[2]);
        split2(x3, ah[3], al[3]);
        #pragma unroll
        for (int nt = 0; nt < 2; nt++) {
            const __nv_bfloat16* bph = Wh + (wn * 16 + nt * 8 + rr) * EWPAD + kb + q * 2;
            const __nv_bfloat16* bpl = Wl + (wn * 16 + nt * 8 + rr) * EWPAD + kb + q * 2;
            uint32_t bh0 = *(const uint32_t*)bph;
            uint32_t bh1 = *(const uint32_t*)(bph + 8);
            uint32_t bl0 = *(const uint32_t*)bpl;
            uint32_t bl1 = *(const uint32_t*)(bpl + 8);
            mma16816(c[nt], ah, bh0, bh1);
            mma16816(c[nt], ah, bl0, bl1);
            mma16816(c[nt], al, bh0, bh1);
        }
    }

    #pragma unroll
    for (int nt = 0; nt < 2; nt++) {
        #pragma unroll
        for (int half = 0; half < 2; half++) {
            int row = m0 + wm * 16 + half * 8 + rr;
            int col = wn * 16 + nt * 8 + q * 2;
            float2 bb = *(const float2*)&bc[col];
            *(__half2*)&h[(size_t)row * HD + 64 + col] =
                __floats2half2_rn(c[nt][half * 2] + bb.x, c[nt][half * 2 + 1] + bb.y);
        }
    }
    for (int i = t; i < 32 * 64; i += 256) {
        int r = i >> 6, col = i & 63;
        int gn = m0 + r;
        h[(size_t)gn * HD + col] = __float2half(emb[(size_t)label[gn] * 64 + col]);
    }
}

// ---------------- tensor-core GEMM (fp16 S in, split in-kernel) --------------
__global__ void __launch_bounds__(256) k_gemm_mma64(
    const __half* __restrict__ S_g,
    const __nv_bfloat16* __restrict__ Wh_g, const __nv_bfloat16* __restrict__ Wl_g,
    const __half* __restrict__ AddIn, const float* __restrict__ bias,
    const __half* __restrict__ res, __half* __restrict__ out, int M, int addres)
{
    extern __shared__ __align__(16) char smraw[];
    __nv_bfloat16* Ah = (__nv_bfloat16*)smraw;
    __nv_bfloat16* Al = Ah + 64 * APAD;
    __nv_bfloat16* Wh = Al + 64 * APAD;
    __nv_bfloat16* Wl = Wh + 128 * APAD;
    int t = threadIdx.x;
    int m0 = blockIdx.x * 64;

    #pragma unroll
    for (int j = 0; j < 8; j++) {
        int i = t + 256 * j;
        int nrow = i >> 4, kg = i & 15;
        *(uint4*)&Wh[nrow * APAD + kg * 8] = ((const uint4*)Wh_g)[i];
        *(uint4*)&Wl[nrow * APAD + kg * 8] = ((const uint4*)Wl_g)[i];
    }
    #pragma unroll
    for (int j = 0; j < 4; j++) {
        int i = t + 256 * j;
        int r = i >> 4, kg = i & 15;
        long gr = m0 + r;
        uint4 v = make_uint4(0u, 0u, 0u, 0u);
        if (gr < M) v = ((const uint4*)S_g)[gr * 16 + kg];
        uint4 hi, lo;
        split_h8(v, hi, lo);
        *(uint4*)&Ah[r * APAD + kg * 8] = hi;
        *(uint4*)&Al[r * APAD + kg * 8] = lo;
    }
    __syncthreads();

    int warp = t >> 5, lane = t & 31;
    int wm = warp & 1, wn = warp >> 1;
    int q = lane & 3, rr = lane >> 2;

    float c[2][4][4];
    #pragma unroll
    for (int i = 0; i < 2; i++)
        #pragma unroll
        for (int j = 0; j < 4; j++)
            c[i][j][0] = c[i][j][1] = c[i][j][2] = c[i][j][3] = 0.f;

    #pragma unroll
    for (int term = 0; term < 3; term++) {
        const __nv_bfloat16* Ab = (term == 2) ? Al : Ah;
        const __nv_bfloat16* Bb = (term == 1) ? Wl : Wh;
        #pragma unroll
        for (int ks = 0; ks < 8; ks++) {
            int kb = ks * 16;
            uint32_t a[2][4];
            #pragma unroll
            for (int mt = 0; mt < 2; mt++) {
                const __nv_bfloat16* ap = Ab + (wm * 32 + mt * 16 + rr) * APAD + kb + q * 2;
                a[mt][0] = *(const uint32_t*)(ap);
                a[mt][1] = *(const uint32_t*)(ap + 8 * APAD);
                a[mt][2] = *(const uint32_t*)(ap + 8);
                a[mt][3] = *(const uint32_t*)(ap + 8 * APAD + 8);
            }
            #pragma unroll
            for (int nt = 0; nt < 4; nt++) {
                const __nv_bfloat16* bp = Bb + (wn * 32 + nt * 8 + rr) * APAD + kb + q * 2;
                uint32_t b0 = *(const uint32_t*)bp;
                uint32_t b1 = *(const uint32_t*)(bp + 8);
                mma16816(c[0][nt], a[0], b0, b1);
                mma16816(c[1][nt], a[1], b0, b1);
            }
        }
    }

    #pragma unroll
    for (int mt = 0; mt < 2; mt++) {
        #pragma unroll
        for (int half = 0; half < 2; half++) {
            int row = m0 + wm * 32 + mt * 16 + half * 8 + rr;
            if (row >= M) continue;
            #pragma unroll
            for (int nt = 0; nt < 4; nt++) {
                int col = wn * 32 + nt * 8 + q * 2;
                size_t o = (size_t)row * HD + col;
                float2 v = make_float2(c[mt][nt][half * 2], c[mt][nt][half * 2 + 1]);
                float2 d = __half22float2(*(const __half2*)&AddIn[o]);
                float2 bb = *(const float2*)&bias[col];
                v.x += d.x + bb.x;
                v.y += d.y + bb.y;
                v.x = fmaxf(v.x, 0.f);
                v.y = fmaxf(v.y, 0.f);
                if (addres) {
                    float2 rv = __half22float2(*(const __half2*)&res[o]);
                    v.x += rv.x; v.y += rv.y;
                }
                *(__half2*)&out[o] = __floats2half2_rn(v.x, v.y);
            }
        }
    }
}

// ---------------- last-layer variant: MMA + fused decode ---------------------
__global__ void __launch_bounds__(256) k_gemm_mma64_dec(
    const __half* __restrict__ S_g,
    const __nv_bfloat16* __restrict__ Wh_g, const __nv_bfloat16* __restrict__ Wl_g,
    const __half* __restrict__ AddIn, const float* __restrict__ bias,
    const float* __restrict__ dW, const float* __restrict__ db,
    float* __restrict__ logits, float* __restrict__ pred, int write_pred)
{
    extern __shared__ __align__(16) char smraw[];
    __nv_bfloat16* Ah = (__nv_bfloat16*)smraw;
    __nv_bfloat16* Al = Ah + 64 * APAD;
    __nv_bfloat16* Wh = Al + 64 * APAD;
    __nv_bfloat16* Wl = Wh + 128 * APAD;
    int t = threadIdx.x;
    int m0 = blockIdx.x * 64;

    #pragma unroll
    for (int j = 0; j < 8; j++) {
        int i = t + 256 * j;
        int nrow = i >> 4, kg = i & 15;
        *(uint4*)&Wh[nrow * APAD + kg * 8] = ((const uint4*)Wh_g)[i];
        *(uint4*)&Wl[nrow * APAD + kg * 8] = ((const uint4*)Wl_g)[i];
    }
    #pragma unroll
    for (int j = 0; j < 4; j++) {
        int i = t + 256 * j;
        int r = i >> 4, kg = i & 15;
        long gr = m0 + r;
        uint4 v = ((const uint4*)S_g)[gr * 16 + kg];
        uint4 hi, lo;
        split_h8(v, hi, lo);
        *(uint4*)&Ah[r * APAD + kg * 8] = hi;
        *(uint4*)&Al[r * APAD + kg * 8] = lo;
    }
    __syncthreads();

    int warp = t >> 5, lane = t & 31;
    int wm = warp & 1, wn = warp >> 1;
    int q = lane & 3, rr = lane >> 2;

    float c[2][4][4];
    #pragma unroll
    for (int i = 0; i < 2; i++)
        #pragma unroll
        for (int j = 0; j < 4; j++)
            c[i][j][0] = c[i][j][1] = c[i][j][2] = c[i][j][3] = 0.f;

    #pragma unroll
    for (int term = 0; term < 3; term++) {
        const __nv_bfloat16* Ab = (term == 2) ? Al : Ah;
        const __nv_bfloat16* Bb = (term == 1) ? Wl : Wh;
        #pragma unroll
        for (int ks = 0; ks < 8; ks++) {
            int kb = ks * 16;
            uint32_t a[2][4];
            #pragma unroll
            for (int mt = 0; mt < 2; mt++) {
                const __nv_bfloat16* ap = Ab + (wm * 32 + mt * 16 + rr) * APAD + kb + q * 2;
                a[mt][0] = *(const uint32_t*)(ap);
                a[mt][1] = *(const uint32_t*)(ap + 8 * APAD);
                a[mt][2] = *(const uint32_t*)(ap + 8);
                a[mt][3] = *(const uint32_t*)(ap + 8 * APAD + 8);
            }
            #pragma unroll
            for (int nt = 0; nt < 4; nt++) {
                const __nv_bfloat16* bp = Bb + (wn * 32 + nt * 8 + rr) * APAD + kb + q * 2;
                uint32_t b0 = *(const uint32_t*)bp;
                uint32_t b1 = *(const uint32_t*)(bp + 8);
                mma16816(c[0][nt], a[0], b0, b1);
                mma16816(c[1][nt], a[1], b0, b1);
            }
        }
    }

    float l0[4] = {0.f, 0.f, 0.f, 0.f};
    float l1[4] = {0.f, 0.f, 0.f, 0.f};
    #pragma unroll
    for (int mt = 0; mt < 2; mt++) {
        #pragma unroll
        for (int half = 0; half < 2; half++) {
            int row = m0 + wm * 32 + mt * 16 + half * 8 + rr;
            int ridx = mt * 2 + half;
            #pragma unroll
            for (int nt = 0; nt < 4; nt++) {
                int col = wn * 32 + nt * 8 + q * 2;
                size_t o = (size_t)row * HD + col;
                float2 v = make_float2(c[mt][nt][half * 2], c[mt][nt][half * 2 + 1]);
                float2 d = __half22float2(*(const __half2*)&AddIn[o]);
                float2 bb = *(const float2*)&bias[col];
                v.x = fmaxf(v.x + d.x + bb.x, 0.f);
                v.y = fmaxf(v.y + d.y + bb.y, 0.f);
                float2 w0 = *(const float2*)&dW[col * 2];
                float2 w1 = *(const float2*)&dW[(col + 1) * 2];
                l0[ridx] += v.x * w0.x + v.y * w1.x;
                l1[ridx] += v.x * w0.y + v.y * w1.y;
            }
        }
    }
    #pragma unroll
    for (int ridx = 0; ridx < 4; ridx++) {
        l0[ridx] += __shfl_xor_sync(0xffffffffu, l0[ridx], 1);
        l0[ridx] += __shfl_xor_sync(0xffffffffu, l0[ridx], 2);
        l1[ridx] += __shfl_xor_sync(0xffffffffu, l1[ridx], 1);
        l1[ridx] += __shfl_xor_sync(0xffffffffu, l1[ridx], 2);
    }
    __syncthreads();
    float* dsm = (float*)smraw;
    if (q == 0) {
        #pragma unroll
        for (int mt = 0; mt < 2; mt++) {
            #pragma unroll
            for (int half = 0; half < 2; half++) {
                int rloc = wm * 32 + mt * 16 + half * 8 + rr;
                int ridx = mt * 2 + half;
                dsm[rloc * 8 + wn * 2 + 0] = l0[ridx];
                dsm[rloc * 8 + wn * 2 + 1] = l1[ridx];
            }
        }
    }
    __syncthreads();
    if (t < 64) {
        float L0 = dsm[t * 8] + dsm[t * 8 + 2] + dsm[t * 8 + 4] + dsm[t * 8 + 6] + db[0];
        float L1 = dsm[t * 8 + 1] + dsm[t * 8 + 3] + dsm[t * 8 + 5] + dsm[t * 8 + 7] + db[1];
        long grow = m0 + t;
        logits[grow * 2]     = L0;
        logits[grow * 2 + 1] = L1;
        if (write_pred) {
            float mx = fmaxf(L0, L1);
            float e0 = expf(L0 - mx), e1 = expf(L1 - mx);
            float s = e0 + e1;
            pred[grow * 2]     = e0 / s;
            pred[grow * 2 + 1] = e1 / s;
        }
    }
}

// ---------------- FFMA GEMM with fused epilogue (small M, fp32 test path) ----
__global__ void __launch_bounds__(256) k_gemm_ep(
    const float* __restrict__ A, const float* __restrict__ W,
    const float* __restrict__ AddIn, const float* __restrict__ bias,
    const float* __restrict__ res, float* __restrict__ out, int M, int flags)
{
    extern __shared__ float sm[];
    float* Ws = sm;
    float* As = sm + 16384;
    int t = threadIdx.x;
    const float4* W4 = (const float4*)W;
    float4* Ws4 = (float4*)Ws;
    #pragma unroll
    for (int i = 0; i < 16; i++) Ws4[t + 256 * i] = W4[t + 256 * i];
    int m0 = blockIdx.x * 64;
    #pragma unroll
    for (int i = 0; i < 8; i++) {
        int idx = t + 256 * i;
        int r = idx >> 5, cc = idx & 31;
        int gr = m0 + r;
        float4 v = (gr < M) ? ((const float4*)A)[(size_t)gr * 32 + cc]
                            : make_float4(0.f, 0.f, 0.f, 0.f);
        *(float4*)&As[r * 132 + cc * 4] = v;
    }
    __syncthreads();
    int c0 = (t & 31) * 4;
    int r0 = (t >> 5) * 8;
    float acc[8][4];
    #pragma unroll
    for (int i = 0; i < 8; i++) { acc[i][0] = acc[i][1] = acc[i][2] = acc[i][3] = 0.f; }
    #pragma unroll 2
    for (int k = 0; k < 128; k++) {
        float4 w = *(const float4*)&Ws[k * 128 + c0];
        #pragma unroll
        for (int i = 0; i < 8; i++) {
            float a = As[(r0 + i) * 132 + k];
            acc[i][0] += a * w.x;
            acc[i][1] += a * w.y;
            acc[i][2] += a * w.z;
            acc[i][3] += a * w.w;
        }
    }
    float4 bb = make_float4(0.f, 0.f, 0.f, 0.f);
    if (flags & F_BIAS) bb = *(const float4*)&bias[c0];
    #pragma unroll
    for (int i = 0; i < 8; i++) {
        int gr = m0 + r0 + i;
        if (gr < M) {
            size_t o = (size_t)gr * HD + c0;
            float4 v = make_float4(acc[i][0] + bb.x, acc[i][1] + bb.y,
                                   acc[i][2] + bb.z, acc[i][3] + bb.w);
            if (flags & F_ADDIN) {
                float4 d = *(const float4*)&AddIn[o];
                v.x += d.x; v.y += d.y; v.z += d.z; v.w += d.w;
            }
            if (flags & F_RELU) {
                v.x = fmaxf(v.x, 0.f); v.y = fmaxf(v.y, 0.f);
                v.z = fmaxf(v.z, 0.f); v.w = fmaxf(v.w, 0.f);
            }
            if (flags & F_ADDRES) {
                float4 rv = *(const float4*)&res[o];
                v.x += rv.x; v.y += rv.y; v.z += rv.z; v.w += rv.w;
            }
            *(float4*)&out[o] = v;
        }
    }
}

// ---------------- mean aggregation (fp32 rows in, fp16 out: Mta) -------------
__global__ void k_agg_f2h(const float* __restrict__ X,
                          const int* __restrict__ offs, const int* __restrict__ csr,
                          __half* __restrict__ out, int n)
{
    int node = (blockIdx.x * blockDim.x + threadIdx.x) >> 5;
    if (node >= n) return;
    int lane = threadIdx.x & 31;
    int s0 = offs[node], s1 = offs[node + 1];
    float4 a = make_float4(0.f, 0.f, 0.f, 0.f);
    for (int e0 = s0; e0 < s1; e0 += 32) {
        int idx = (e0 + lane < s1) ? csr[e0 + lane] : 0;
        int m = min(32, s1 - e0);
        #pragma unroll 8
        for (int j = 0; j < m; j++) {
            int s = __shfl_sync(0xffffffffu, idx, j);
            float4 v = *(const float4*)&X[(size_t)s * HD + lane * 4];
            a.x += v.x; a.y += v.y; a.z += v.z; a.w += v.w;
        }
    }
    float inv = 1.f / (float)((s1 - s0) > 0 ? (s1 - s0) : 1);
    __half2 o01 = __floats2half2_rn(a.x * inv, a.y * inv);
    __half2 o23 = __floats2half2_rn(a.z * inv, a.w * inv);
    uint2 pk = make_uint2(*(uint32_t*)&o01, *(uint32_t*)&o23);
    *(uint2*)&out[(size_t)node * HD + lane * 4] = pk;
}

// ---------------- mean aggregation (fp16 rows in, fp32 out: St) --------------
__global__ void k_agg_h(const __half* __restrict__ X,
                        const int* __restrict__ offs, const int* __restrict__ csr,
                        float* __restrict__ out, int n)
{
    int node = (blockIdx.x * blockDim.x + threadIdx.x) >> 5;
    if (node >= n) return;
    int lane = threadIdx.x & 31;
    int s0 = offs[node], s1 = offs[node + 1];
    float4 a = make_float4(0.f, 0.f, 0.f, 0.f);
    for (int e0 = s0; e0 < s1; e0 += 32) {
        int idx = (e0 + lane < s1) ? csr[e0 + lane] : 0;
        int m = min(32, s1 - e0);
        #pragma unroll 8
        for (int j = 0; j < m; j++) {
            int s = __shfl_sync(0xffffffffu, idx, j);
            uint2 raw = *(const uint2*)&X[(size_t)s * HD + lane * 4];
            float2 f01 = __half22float2(*(__half2*)&raw.x);
            float2 f23 = __half22float2(*(__half2*)&raw.y);
            a.x += f01.x; a.y += f01.y; a.z += f23.x; a.w += f23.y;
        }
    }
    float inv = 1.f / (float)((s1 - s0) > 0 ? (s1 - s0) : 1);
    *(float4*)&out[(size_t)node * HD + lane * 4] =
        make_float4(a.x * inv, a.y * inv, a.z * inv, a.w * inv);
}

// ---------------- mean aggregation (fp16 rows in, fp16 out: S) ---------------
__global__ void k_agg_s_h(const __half* __restrict__ X,
                          const int* __restrict__ offs, const int* __restrict__ csr,
                          __half* __restrict__ S, int n)
{
    int node = (blockIdx.x * blockDim.x + threadIdx.x) >> 5;
    if (node >= n) return;
    int lane = threadIdx.x & 31;
    int s0 = offs[node], s1 = offs[node + 1];
    float4 a = make_float4(0.f, 0.f, 0.f, 0.f);
    for (int e0 = s0; e0 < s1; e0 += 32) {
        int idx = (e0 + lane < s1) ? csr[e0 + lane] : 0;
        int m = min(32, s1 - e0);
        #pragma unroll 8
        for (int j = 0; j < m; j++) {
            int s = __shfl_sync(0xffffffffu, idx, j);
            uint2 raw = *(const uint2*)&X[(size_t)s * HD + lane * 4];
            float2 f01 = __half22float2(*(__half2*)&raw.x);
            float2 f23 = __half22float2(*(__half2*)&raw.y);
            a.x += f01.x; a.y += f01.y; a.z += f23.x; a.w += f23.y;
        }
    }
    float inv = 1.f / (float)((s1 - s0) > 0 ? (s1 - s0) : 1);
    __half2 o01 = __floats2half2_rn(a.x * inv, a.y * inv);
    __half2 o23 = __floats2half2_rn(a.z * inv, a.w * inv);
    uint2 pk = make_uint2(*(uint32_t*)&o01, *(uint32_t*)&o23);
    *(uint2*)&S[(size_t)node * HD + lane * 4] = pk;
}

// ---------------- launch ----------------------------------------------------
extern "C" void kernel_launch(void* const* d_in, const int* in_sizes, int n_in,
                              void* d_out, int out_size)
{
    const int*   ast_label   = (const int*)d_in[0];
    const float* ast_content = (const float*)d_in[1];
    const int* src_aa = (const int*)d_in[2];
    const int* dst_aa = (const int*)d_in[3];
    const int* src_at = (const int*)d_in[4];
    const int* dst_at = (const int*)d_in[5];
    const int* src_ta = (const int*)d_in[6];
    const int* dst_ta = (const int*)d_in[7];
    int E_aa = in_sizes[2], E_at = in_sizes[4], E_ta = in_sizes[6];

    int p = 8;
    if (n_in > 8 && in_sizes[8] == 1) p = 9;
    const float* emb    = (const float*)d_in[p + 0];
    const float* Wc     = (const float*)d_in[p + 1];
    const float* bc     = (const float*)d_in[p + 2];
    const float* temb   = (const float*)d_in[p + 3];
    const float* W_aa   = (const float*)d_in[p + 4];
    const float* W_at   = (const float*)d_in[p + 5];
    const float* W_ta   = (const float*)d_in[p + 6];
    const float* b_ast  = (const float*)d_in[p + 7];
    const float* b_test = (const float*)d_in[p + 8];
    const float* dW     = (const float*)d_in[p + 9];
    const float* db     = (const float*)d_in[p + 10];

    float* F = nullptr;
    int*   I = nullptr;
    cudaGetSymbolAddress((void**)&F, g_f);
    cudaGetSymbolAddress((void**)&I, g_i);

    cudaFuncSetAttribute(k_gemm_ep,        cudaFuncAttributeMaxDynamicSharedMemorySize, 99328);
    cudaFuncSetAttribute(k_gemm_mma64,     cudaFuncAttributeMaxDynamicSharedMemorySize, 104448);
    cudaFuncSetAttribute(k_gemm_mma64_dec, cudaFuncAttributeMaxDynamicSharedMemorySize, 104448);
    cudaFuncSetAttribute(k_enc_mma,        cudaFuncAttributeMaxDynamicSharedMemorySize, SM_ENC_TOT);

    __half* hA = (__half*)(F + F_HA);
    __half* hB = (__half*)(F + F_HB);
    __half* S   = (__half*)(F + F_S);
    __half* Mta = (__half*)(F + F_MTA);
    float* Xta = F + F_XTA;  float* St  = F + F_STB;
    float* hTA = F + F_HTA;  float* hTB = F + F_HTB;
    __nv_bfloat16* Whg  = (__nv_bfloat16*)(F + F_WS);
    __nv_bfloat16* Wlg  = (__nv_bfloat16*)(F + F_WS + 40960u);
    __nv_bfloat16* Wchg = (__nv_bfloat16*)(F + F_WC);
    __nv_bfloat16* Wclg = (__nv_bfloat16*)(F + F_WC + 8192u);

    int* off_aa = I + I_OFF_AA; int* off_ta = I + I_OFF_TA; int* off_at = I + I_OFF_AT;
    int* cur_aa = I + I_CUR_AA; int* cur_ta = I + I_CUR_TA; int* cur_at = I + I_CUR_AT;
    int* csr_aa = I + I_CSR_AA; int* csr_ta = I + I_CSR_TA; int* csr_at = I + I_CSR_AT;
    int* part0 = I + I_PART0; int* poff0 = I + I_POFF0;
    int* part1 = I + I_PART1; int* poff1 = I + I_POFF1;
    int* part2 = I + I_PART2; int* poff2 = I + I_POFF2;

    int nb_ast  = div_up(N_AST, 1024);
    int nb_test = div_up(N_TEST, 1024);

    cudaStream_t s0 = 0, s1 = g_sx.s1, s2 = g_sx.s2;
    cudaEvent_t* ev = g_sx.ev;

    cudaEventRecord(ev[EV_ROOT], s0);
    cudaStreamWaitEvent(s1, ev[EV_ROOT], 0);
    cudaStreamWaitEvent(s2, ev[EV_ROOT], 0);

    // --- s0: aa CSR + split_wc + encode + split_w ---
    k_zero_int<<<div_up(N_AST, 256), 256, 0, s0>>>(cur_aa, N_AST);
    k_hist<<<div_up(E_aa, 256), 256, 0, s0>>>(dst_aa, cur_aa, E_aa);
    k_blocksum<<<nb_ast, 1024, 0, s0>>>(cur_aa, part0, N_AST);
    k_exscan<<<1, 1024, 0, s0>>>(part0, poff0, nb_ast);
    k_scan_apply<<<nb_ast, 1024, 0, s0>>>(cur_aa, poff0, off_aa, cur_aa, N_AST);
    k_build<<<div_up(E_aa, 256), 256, 0, s0>>>(dst_aa, src_aa, cur_aa, csr_aa, E_aa);
    k_split_wc<<<div_up(16384, 256), 256, 0, s0>>>(Wc, Wchg, Wclg);
    k_enc_mma<<<N_AST / 32, 256, SM_ENC_TOT, s0>>>(ast_label, ast_content, emb,
                                                   Wchg, Wclg, bc, hA);
    cudaEventRecord(ev[EV_ENC], s0);
    k_split_w<<<div_up(NLAYERS * 16384, 256), 256, 0, s0>>>(W_aa, Whg, Wlg);

    // --- s1: ta CSR + init_test ---
    k_zero_int<<<div_up(N_AST, 256), 256, 0, s1>>>(cur_ta, N_AST);
    k_hist<<<div_up(E_ta, 256), 256, 0, s1>>>(dst_ta, cur_ta, E_ta);
    k_blocksum<<<nb_ast, 1024, 0, s1>>>(cur_ta, part1, N_AST);
    k_exscan<<<1, 1024, 0, s1>>>(part1, poff1, nb_ast);
    k_scan_apply<<<nb_ast, 1024, 0, s1>>>(cur_ta, poff1, off_ta, cur_ta, N_AST);
    k_build<<<div_up(E_ta, 256), 256, 0, s1>>>(dst_ta, src_ta, cur_ta, csr_ta, E_ta);
    k_init_test<<<div_up(N_TEST * HD, 256), 256, 0, s1>>>(temb, hTA);
    cudaEventRecord(ev[EV_INITT], s1);

    // --- s2: at CSR ---
    k_zero_int<<<div_up(N_TEST, 256), 256, 0, s2>>>(cur_at, N_TEST);
    k_hist<<<div_up(E_at, 256), 256, 0, s2>>>(dst_at, cur_at, E_at);
    k_blocksum<<<nb_test, 1024, 0, s2>>>(cur_at, part2, N_TEST);
    k_exscan<<<1, 1024, 0, s2>>>(part2, poff2, nb_test);
    k_scan_apply<<<nb_test, 1024, 0, s2>>>(cur_at, poff2, off_at, cur_at, N_TEST);
    k_build<<<div_up(E_at, 256), 256, 0, s2>>>(dst_at, src_at, cur_at, csr_at, E_at);
    cudaStreamWaitEvent(s2, ev[EV_ENC], 0);
    cudaStreamWaitEvent(s2, ev[EV_INITT], 0);

    float* logits = (float*)d_out;
    int write_pred = (out_size >= 4 * N_AST);
    float* pred = logits + 2 * N_AST;

    // --- 5 GCN layers, 3-stream pipeline ---
    const __half* ia = hA; const float* it = hTA;
    __half* oa = hB; float* ot = hTB;
    for (int l = 0; l < NLAYERS; l++) {
        int add  = (l == 1 || l == 3);
        int last = (l == NLAYERS - 1);

        // s2: test-node path (aggSt -> gemmAt)   [dead at last layer]
        if (!last) {
            if (l > 0) cudaStreamWaitEvent(s2, ev[EV_MMA(l - 1)], 0);
            k_agg_h<<<div_up(N_TEST * 32, 256), 256, 0, s2>>>(ia, off_at, csr_at, St, N_TEST);
            k_gemm_ep<<<div_up(N_TEST, 64), 256, 99328, s2>>>(St, W_at + (size_t)l * HD * HD,
                nullptr, b_test + l * HD, it, ot, N_TEST,
                F_BIAS | F_RELU | (add ? F_ADDRES : 0));
            cudaEventRecord(ev[EV_AT(l)], s2);
        }

        // s1: Mta chain (gemmXta -> aggMta fp16)
        if (l > 0) cudaStreamWaitEvent(s1, ev[EV_AT(l - 1)], 0);
        k_gemm_ep<<<div_up(N_TEST, 64), 256, 99328, s1>>>(it, W_ta + (size_t)l * HD * HD,
            nullptr, nullptr, nullptr, Xta, N_TEST, 0);
        if (l > 0) cudaStreamWaitEvent(s1, ev[EV_MMA(l - 1)], 0);
        k_agg_f2h<<<div_up(N_AST * 32, 256), 256, 0, s1>>>(Xta, off_ta, csr_ta, Mta, N_AST);
        cudaEventRecord(ev[EV_MTA(l)], s1);

        // s0: big gather (fp16 S out) + tensor-core GEMM
        k_agg_s_h<<<div_up(N_AST * 32, 256), 256, 0, s0>>>(ia, off_aa, csr_aa, S, N_AST);
        cudaStreamWaitEvent(s0, ev[EV_MTA(l)], 0);
        if (!last) {
            k_gemm_mma64<<<div_up(N_AST, 64), 256, 104448, s0>>>(S,
                Whg + (size_t)l * 16384, Wlg + (size_t)l * 16384,
                Mta, b_ast + l * HD, ia, oa, N_AST, add);
            cudaEventRecord(ev[EV_MMA(l)], s0);
        } else {
            k_gemm_mma64_dec<<<N_AST / 64, 256, 104448, s0>>>(S,
                Whg + (size_t)l * 16384, Wlg + (size_t)l * 16384,
                Mta, b_ast + l * HD, dW, db, logits, pred, write_pred);
        }

        const __half* ta = ia; ia = oa; oa = (__half*)ta;
        if (!last) { const float* tt = it; it = ot; ot = (float*)tt; }
    }
}